// round 8
// baseline (speedup 1.0000x reference)
#include <cuda_runtime.h>
#include <cuda_fp16.h>
#include <cstdint>

#define Bq 512
#define Hq 512
#define Lq 512
#define Iq 32
#define DTF 0.042f
#define NCTA 128
#define NTHR 256

// ---- SMEM layout (bytes) ----
#define OFF_A   0
#define OFF_B   104448
#define OFF_X   156672
#define OFF_BX  166912
#define OFF_T   172032
#define OFF_O   181248
#define OFF_SC  190464
#define SMEM_TOT 190848

#define A_PART  17408u
#define A_BUF   34816u
#define B_PART  8704u
#define B_BUF   17408u
#define X_PART  5120u
#define BX_PART 2560u
#define T_PART  4608u

// ---- persistent device state (hy / T^T double-buffered by step parity) ----
__device__ __align__(256) __half g_hy_hi[2][Bq*Hq], g_hy_lo[2][Bq*Hq];
__device__ __align__(256) __half g_Tt_hi[2][Hq*Bq], g_Tt_lo[2][Hq*Bq];  // [h][b]
__device__ __align__(256) __half g_W1_hi[Hq*Hq], g_W1_lo[Hq*Hq];        // h2h^T: [h][k]
__device__ __align__(256) __half g_W2_hi[Hq*Hq], g_W2_lo[Hq*Hq];        // -h2hT: [b][j]
__device__ unsigned g_flag_hy[8][16];   // [b_tile][h_tile]: hy state index published
__device__ unsigned g_flag_T [16][8];   // [h_tile][b_tile]: T  step+1 published
__device__ unsigned g_bar_count = 0u;
__device__ volatile unsigned g_bar_gen = 0u;

__device__ __forceinline__ uint32_t smem_u32(const void* p) {
    uint32_t a;
    asm("{ .reg .u64 t; cvta.to.shared.u64 t, %1; cvt.u32.u64 %0, t; }" : "=r"(a) : "l"(p));
    return a;
}
#define CP_ASYNC16(dst, src) \
    asm volatile("cp.async.cg.shared.global [%0], [%1], 16;" :: "r"(dst), "l"(src) : "memory")
#define CP_COMMIT() asm volatile("cp.async.commit_group;" ::: "memory")
#define CP_WAIT0()  asm volatile("cp.async.wait_group 0;" ::: "memory")
#define CP_WAIT1()  asm volatile("cp.async.wait_group 1;" ::: "memory")
#define LDSM4(r0,r1,r2,r3, addr) \
    asm volatile("ldmatrix.sync.aligned.m8n8.x4.shared.b16 {%0,%1,%2,%3}, [%4];" \
        : "=r"(r0), "=r"(r1), "=r"(r2), "=r"(r3) : "r"(addr))

__device__ __forceinline__ void mma16816(float* c, uint32_t a0, uint32_t a1, uint32_t a2,
                                         uint32_t a3, uint32_t b0, uint32_t b1) {
    asm volatile(
        "mma.sync.aligned.m16n8k16.row.col.f32.f16.f16.f32 "
        "{%0,%1,%2,%3}, {%4,%5,%6,%7}, {%8,%9}, {%0,%1,%2,%3};"
        : "+f"(c[0]), "+f"(c[1]), "+f"(c[2]), "+f"(c[3])
        : "r"(a0), "r"(a1), "r"(a2), "r"(a3), "r"(b0), "r"(b1));
}

// acquire-poll a flag until it reaches target
__device__ __forceinline__ void wait_ge(const unsigned* p, unsigned tgt) {
    unsigned v;
    #pragma unroll 1
    do {
        asm volatile("ld.acquire.gpu.global.u32 %0, [%1];" : "=r"(v) : "l"(p) : "memory");
    } while (v < tgt);
}
__device__ __forceinline__ void publish(unsigned* p, unsigned v) {
    __threadfence();
    asm volatile("st.release.gpu.global.u32 [%0], %1;" :: "l"(p), "r"(v) : "memory");
}

// ---- staging: BK=128, padded SMEM rows of 272B ----
__device__ __forceinline__ void stageA128(uint32_t dst0, const __half* __restrict__ ghi,
                                          const __half* __restrict__ glo,
                                          int row0, int k0, int tid) {
    #pragma unroll
    for (int e = 0; e < 8; ++e) {
        int idx = tid + e * NTHR;
        const __half* g = (e < 4) ? ghi : glo;
        uint32_t po = (e < 4) ? 0u : A_PART;
        int rem = idx & 1023, r = rem >> 4, seg = rem & 15;
        CP_ASYNC16(dst0 + po + (uint32_t)(r * 272 + seg * 16),
                   g + (size_t)(row0 + r) * 512 + k0 + seg * 8);
    }
}
__device__ __forceinline__ void stageB128(uint32_t dst0, const __half* __restrict__ ghi,
                                          const __half* __restrict__ glo,
                                          int row0, int k0, int tid) {
    #pragma unroll
    for (int e = 0; e < 4; ++e) {
        int idx = tid + e * NTHR;
        const __half* g = (e < 2) ? ghi : glo;
        uint32_t po = (e < 2) ? 0u : B_PART;
        int rem = idx & 511, r = rem >> 4, seg = rem & 15;
        CP_ASYNC16(dst0 + po + (uint32_t)(r * 272 + seg * 16),
                   g + (size_t)(row0 + r) * 512 + k0 + seg * 8);
    }
}

template<int NKS>
__device__ __forceinline__ void compute_chunk(
    uint32_t aBase, uint32_t aPart, uint32_t aStr,
    uint32_t bBase, uint32_t bPart, uint32_t bStr,
    int mw, int nw, int lane, float acc[2][4])
{
    const int m = lane >> 3, rr = lane & 7;
    const uint32_t aAddr = aBase + (uint32_t)(mw * 16 + (m & 1) * 8 + rr) * aStr
                         + (uint32_t)((m >> 1) * 16);
    const uint32_t bAddr = bBase + (uint32_t)(nw * 16 + (m >> 1) * 8 + rr) * bStr
                         + (uint32_t)((m & 1) * 16);
    #pragma unroll
    for (int ks = 0; ks < NKS; ++ks) {
        uint32_t ah0, ah1, ah2, ah3, al0, al1, al2, al3;
        LDSM4(ah0, ah1, ah2, ah3, aAddr + ks * 32);
        LDSM4(al0, al1, al2, al3, aAddr + aPart + ks * 32);
        uint32_t bh0, bh1, bh2, bh3, bl0, bl1, bl2, bl3;
        LDSM4(bh0, bh1, bh2, bh3, bAddr + ks * 32);
        LDSM4(bl0, bl1, bl2, bl3, bAddr + bPart + ks * 32);
        mma16816(acc[0], ah0, ah1, ah2, ah3, bh0, bh1);
        mma16816(acc[0], ah0, ah1, ah2, ah3, bl0, bl1);
        mma16816(acc[0], al0, al1, al2, al3, bh0, bh1);
        mma16816(acc[1], ah0, ah1, ah2, ah3, bh2, bh3);
        mma16816(acc[1], ah0, ah1, ah2, ah3, bl2, bl3);
        mma16816(acc[1], al0, al1, al2, al3, bh2, bh3);
    }
}

__device__ __forceinline__ void grid_barrier(unsigned gen) {
    __syncthreads();
    if (threadIdx.x == 0) {
        __threadfence();
        if (atomicAdd(&g_bar_count, 1u) == (unsigned)(NCTA - 1)) {
            g_bar_count = 0u;
            __threadfence();
            g_bar_gen = gen + 1u;
        } else {
            while (g_bar_gen == gen) { }
            __threadfence();
        }
    }
    __syncthreads();
}

__global__ void __launch_bounds__(NTHR, 1) coesn_mma(
    const float* __restrict__ x,    const float* __restrict__ x2h,
    const float* __restrict__ h2h,  const float* __restrict__ h2hT,
    const float* __restrict__ bias, const float* __restrict__ gamma,
    const float* __restrict__ eps,  float* __restrict__ out, int write_final)
{
    extern __shared__ __align__(16) char smem[];
    const uint32_t sb = smem_u32(smem);
    const int tid = threadIdx.x;
    const int w = tid >> 5, lane = tid & 31;
    const int mw = w & 3, nw = w >> 2;
    const int bidx = blockIdx.x;
    const int bt = bidx >> 4, ht = bidx & 15;
    const int b0 = bt * 64, h0 = ht * 32;

    unsigned gen = g_bar_gen;

    // ---- init: split weights, zero hy buf0, reset own flags ----
    const int gtid = bidx * NTHR + tid;
    #pragma unroll 1
    for (int e = 0; e < 8; ++e) {
        int idx = gtid + e * (NCTA * NTHR);
        int r = idx >> 9, c = idx & 511;
        float v1 = h2h[(size_t)c * Hq + r];
        __half h1 = __float2half_rn(v1);
        g_W1_hi[idx] = h1;
        g_W1_lo[idx] = __float2half_rn(v1 - __half2float(h1));
        float v2 = -h2hT[idx];
        __half h2v = __float2half_rn(v2);
        g_W2_hi[idx] = h2v;
        g_W2_lo[idx] = __float2half_rn(v2 - __half2float(h2v));
        __half z = __float2half_rn(0.f);
        g_hy_hi[0][idx] = z;
        g_hy_lo[0][idx] = z;
    }
    if (tid == 0) { g_flag_hy[bt][ht] = 0u; g_flag_T[ht][bt] = 0u; }
    // BX = x2h^T slice [32 h][32 i]
    #pragma unroll
    for (int e = 0; e < 8; ++e) {
        int idx = tid + e * NTHR;
        int part = (idx >= 1024);
        int rem = idx & 1023, r = rem >> 5, ii = rem & 31;
        float v = x2h[(size_t)ii * Hq + h0 + r];
        __half hv = __float2half_rn(v);
        __half val = part ? __float2half_rn(v - __half2float(hv)) : hv;
        *(__half*)(smem + OFF_BX + part * BX_PART + r * 80 + ii * 2) = val;
    }
    if (tid < 32) {
        ((float*)(smem + OFF_SC))[tid]      = bias[h0 + tid];
        ((float*)(smem + OFF_SC))[32 + tid] = gamma[h0 + tid];
        ((float*)(smem + OFF_SC))[64 + tid] = eps[h0 + tid];
    }
    const float* scp = (const float*)(smem + OFF_SC);
    grid_barrier(gen); gen++;   // weights + zeros + flag resets visible chip-wide

    float hyr[2][4], hzr[2][4];
    #pragma unroll
    for (int p = 0; p < 2; ++p)
        #pragma unroll
        for (int j = 0; j < 4; ++j) { hyr[p][j] = 0.f; hzr[p][j] = 0.f; }

    #pragma unroll 1
    for (int t = 0; t < Lq; ++t) {
        const int pt = t & 1;
        const __half* hyH = g_hy_hi[pt];
        const __half* hyL = g_hy_lo[pt];
        const __half* TtH = g_Tt_hi[pt];
        const __half* TtL = g_Tt_lo[pt];

        // ===== Phase 1: D1 = hy @ h2h; T^T = tanh(D1 + bias)^T =====
        float acc[2][4];
        #pragma unroll
        for (int p = 0; p < 2; ++p)
            #pragma unroll
            for (int j = 0; j < 4; ++j) acc[p][j] = 0.f;

        stageB128(sb + OFF_B, g_W1_hi, g_W1_lo, h0, 0, tid);        // static, no wait
        wait_ge(&g_flag_hy[bt][(tid & 3)], (unsigned)t);
        stageA128(sb + OFF_A, hyH, hyL, b0, 0, tid);
        CP_COMMIT();
        stageB128(sb + OFF_B + B_BUF, g_W1_hi, g_W1_lo, h0, 128, tid);
        wait_ge(&g_flag_hy[bt][4 + (tid & 3)], (unsigned)t);
        stageA128(sb + OFF_A + A_BUF, hyH, hyL, b0, 128, tid);
        CP_COMMIT();
        #pragma unroll 1
        for (int kc = 0; kc < 4; ++kc) {
            if (kc < 3) { CP_WAIT1(); } else { CP_WAIT0(); }
            __syncthreads();
            if (kc + 2 < 4) {
                stageB128(sb + OFF_B + (uint32_t)((kc + 2) % 3) * B_BUF,
                          g_W1_hi, g_W1_lo, h0, (kc + 2) * 128, tid);
                wait_ge(&g_flag_hy[bt][4 * (kc + 2) + (tid & 3)], (unsigned)t);
                stageA128(sb + OFF_A + (uint32_t)((kc + 2) % 3) * A_BUF,
                          hyH, hyL, b0, (kc + 2) * 128, tid);
                CP_COMMIT();
            }
            compute_chunk<8>(sb + OFF_A + (uint32_t)(kc % 3) * A_BUF, A_PART, 272u,
                             sb + OFF_B + (uint32_t)(kc % 3) * B_BUF, B_PART, 272u,
                             mw, nw, lane, acc);
        }

        // tanh + split -> T smem -> global stripe, publish
        #pragma unroll
        for (int p = 0; p < 2; ++p) {
            #pragma unroll
            for (int j = 0; j < 4; ++j) {
                int hc = nw * 16 + p * 8 + 2 * (lane & 3) + (j & 1);
                int bl = mw * 16 + (lane >> 2) + ((j >> 1) * 8);
                float v = acc[p][j] + scp[hc];
                float e2 = __expf(2.f * v);
                float tv = 1.f - 2.f / (e2 + 1.f);
                __half hv = __float2half_rn(tv);
                __half lv = __float2half_rn(tv - __half2float(hv));
                *(__half*)(smem + OFF_T + hc * 144 + bl * 2) = hv;
                *(__half*)(smem + OFF_T + T_PART + hc * 144 + bl * 2) = lv;
            }
        }
        __syncthreads();
        #pragma unroll
        for (int e = 0; e < 2; ++e) {
            int idx = tid + e * NTHR;
            int part = idx >> 8;
            int rem = idx & 255, r = rem >> 3, q = rem & 7;
            uint4 val = *(const uint4*)(smem + OFF_T + part * T_PART + r * 144 + q * 16);
            __half* g = part ? g_Tt_lo[pt] : g_Tt_hi[pt];
            *(uint4*)(g + (size_t)(h0 + r) * 512 + b0 + q * 8) = val;
        }
        __syncthreads();
        if (tid == 0) publish(&g_flag_T[ht][bt], (unsigned)(t + 1));

        // ===== Phase 2: D2 = x_t @ x2h - h2hT @ T =====
        stageA128(sb + OFF_A, g_W2_hi, g_W2_lo, b0, 0, tid);        // static, no wait
        wait_ge(&g_flag_T[ht][(tid & 1)], (unsigned)(t + 1));
        stageB128(sb + OFF_B, TtH, TtL, h0, 0, tid);
        CP_COMMIT();
        stageA128(sb + OFF_A + A_BUF, g_W2_hi, g_W2_lo, b0, 128, tid);
        wait_ge(&g_flag_T[ht][2 + (tid & 1)], (unsigned)(t + 1));
        stageB128(sb + OFF_B + B_BUF, TtH, TtL, h0, 128, tid);
        CP_COMMIT();
        // x_t split -> X SMEM (visibility covered by kc=0 __syncthreads)
        #pragma unroll
        for (int e = 0; e < 2; ++e) {
            int idx = tid + e * NTHR;
            int r = idx >> 3, q = idx & 7;
            float4 v = *(const float4*)(x + (size_t)(b0 + r) * (Lq * Iq)
                                          + (size_t)t * Iq + q * 4);
            __half h0v = __float2half_rn(v.x), h1v = __float2half_rn(v.y);
            __half h2v = __float2half_rn(v.z), h3v = __float2half_rn(v.w);
            __half l0v = __float2half_rn(v.x - __half2float(h0v));
            __half l1v = __float2half_rn(v.y - __half2float(h1v));
            __half l2v = __float2half_rn(v.z - __half2float(h2v));
            __half l3v = __float2half_rn(v.w - __half2float(h3v));
            char* dh = smem + OFF_X + r * 80 + q * 8;
            char* dl = dh + X_PART;
            *(__half2*)(dh)     = __halves2half2(h0v, h1v);
            *(__half2*)(dh + 4) = __halves2half2(h2v, h3v);
            *(__half2*)(dl)     = __halves2half2(l0v, l1v);
            *(__half2*)(dl + 4) = __halves2half2(l2v, l3v);
        }
        #pragma unroll
        for (int p = 0; p < 2; ++p)
            #pragma unroll
            for (int j = 0; j < 4; ++j) acc[p][j] = 0.f;
        #pragma unroll 1
        for (int kc = 0; kc < 4; ++kc) {
            if (kc < 3) { CP_WAIT1(); } else { CP_WAIT0(); }
            __syncthreads();
            if (kc + 2 < 4) {
                stageA128(sb + OFF_A + (uint32_t)((kc + 2) % 3) * A_BUF,
                          g_W2_hi, g_W2_lo, b0, (kc + 2) * 128, tid);
                wait_ge(&g_flag_T[ht][2 * (kc + 2) + (tid & 1)], (unsigned)(t + 1));
                stageB128(sb + OFF_B + (uint32_t)((kc + 2) % 3) * B_BUF,
                          TtH, TtL, h0, (kc + 2) * 128, tid);
                CP_COMMIT();
            }
            if (kc == 0) {
                compute_chunk<2>(sb + OFF_X, X_PART, 80u,
                                 sb + OFF_BX, BX_PART, 80u, mw, nw, lane, acc);
            }
            compute_chunk<8>(sb + OFF_A + (uint32_t)(kc % 3) * A_BUF, A_PART, 272u,
                             sb + OFF_B + (uint32_t)(kc % 3) * B_BUF, B_PART, 272u,
                             mw, nw, lane, acc);
        }

        // integrate; hy -> O smem tile
        #pragma unroll
        for (int p = 0; p < 2; ++p) {
            #pragma unroll
            for (int j = 0; j < 4; ++j) {
                int hc = nw * 16 + p * 8 + 2 * (lane & 3) + (j & 1);
                int bl = mw * 16 + (lane >> 2) + ((j >> 1) * 8);
                float hy = hyr[p][j], hz = hzr[p][j];
                hz += DTF * (acc[p][j] - scp[32 + hc] * hy - scp[64 + hc] * hz);
                hy += DTF * hz;
                hzr[p][j] = hz; hyr[p][j] = hy;
                *(float*)(smem + OFF_O + bl * 144 + hc * 4) = hy;
            }
        }
        __syncthreads();
        {
            __half* ghyH = g_hy_hi[(t + 1) & 1];
            __half* ghyL = g_hy_lo[(t + 1) & 1];
            #pragma unroll
            for (int e = 0; e < 2; ++e) {
                int idx = tid + e * NTHR;
                int r = idx >> 3, q = idx & 7;
                float4 v = *(const float4*)(smem + OFF_O + r * 144 + q * 16);
                *(float4*)(out + (size_t)(b0 + r) * (Lq * Hq) + (size_t)t * Hq
                               + h0 + q * 4) = v;
                __half a0 = __float2half_rn(v.x), a1 = __float2half_rn(v.y);
                __half a2 = __float2half_rn(v.z), a3 = __float2half_rn(v.w);
                __half c0 = __float2half_rn(v.x - __half2float(a0));
                __half c1 = __float2half_rn(v.y - __half2float(a1));
                __half c2 = __float2half_rn(v.z - __half2float(a2));
                __half c3 = __float2half_rn(v.w - __half2float(a3));
                size_t o = (size_t)(b0 + r) * 512 + h0 + q * 4;
                *(__half2*)(ghyH + o)     = __halves2half2(a0, a1);
                *(__half2*)(ghyH + o + 2) = __halves2half2(a2, a3);
                *(__half2*)(ghyL + o)     = __halves2half2(c0, c1);
                *(__half2*)(ghyL + o + 2) = __halves2half2(c2, c3);
            }
        }
        __syncthreads();
        if (tid == 0) publish(&g_flag_hy[bt][ht], (unsigned)(t + 1));
    }

    // final hy (second output)
    if (write_final) {
        #pragma unroll
        for (int p = 0; p < 2; ++p) {
            #pragma unroll
            for (int j = 0; j < 4; ++j) {
                int hc = nw * 16 + p * 8 + 2 * (lane & 3) + (j & 1);
                int bl = mw * 16 + (lane >> 2) + ((j >> 1) * 8);
                out[(size_t)Bq * Lq * Hq + (size_t)(b0 + bl) * Hq + h0 + hc] = hyr[p][j];
            }
        }
    }
}

extern "C" void kernel_launch(void* const* d_in, const int* in_sizes, int n_in,
                              void* d_out, int out_size) {
    const float* x    = (const float*)d_in[0];
    const float* x2h  = (const float*)d_in[1];
    const float* h2h  = (const float*)d_in[2];
    const float* h2hT = (const float*)d_in[3];
    const float* bias = (const float*)d_in[4];
    const float* gam  = (const float*)d_in[5];
    const float* eps  = (const float*)d_in[6];
    (void)in_sizes; (void)n_in;

    cudaFuncSetAttribute(coesn_mma, cudaFuncAttributeMaxDynamicSharedMemorySize, SMEM_TOT);
    const int write_final = (out_size >= Bq * Lq * Hq + Bq * Hq) ? 1 : 0;
    coesn_mma<<<NCTA, NTHR, SMEM_TOT>>>(x, x2h, h2h, h2hT, bias, gam, eps,
                                        (float*)d_out, write_final);
}

// round 9
// speedup vs baseline: 1.5336x; 1.5336x over previous
#include <cuda_runtime.h>
#include <cuda_fp16.h>
#include <cstdint>

#define Bq 512
#define Hq 512
#define Lq 512
#define Iq 32
#define DTF 0.042f
#define NCTA 256
#define NTHR 128

// ---- SMEM layout (bytes) ----
// A bufs: 3 x (2 part x 32 rows x 144B) = 27648
// B bufs: 3 x (2 part x 32 rows x 144B) = 27648
// X:  2 part x (32 x 80B) = 5120
// BX: 2 part x (32 x 80B) = 5120
// T:  2 part x (32 x 80B) = 5120
// O:  32 x 144B = 4608
// SC: 3 x 32 floats = 384
#define OFF_A   0
#define OFF_B   27648
#define OFF_X   55296
#define OFF_BX  60416
#define OFF_T   65536
#define OFF_O   70656
#define OFF_SC  75264
#define SMEM_TOT 75648

#define A_PART  4608u
#define A_BUF   9216u
#define X_PART  2560u
#define BX_PART 2560u
#define T_PART  2560u

// ---- persistent device state ----
__device__ __align__(256) __half g_hy_hi[Bq*Hq], g_hy_lo[Bq*Hq];
__device__ __align__(256) __half g_Tt_hi[Hq*Bq], g_Tt_lo[Hq*Bq];   // T^T: [h][b]
__device__ __align__(256) __half g_W1_hi[Hq*Hq], g_W1_lo[Hq*Hq];   // h2h^T: [h][k]
__device__ __align__(256) __half g_W2_hi[Hq*Hq], g_W2_lo[Hq*Hq];   // -h2hT: [b][j]
__device__ unsigned g_bar_count = 0u;
__device__ volatile unsigned g_bar_gen = 0u;

__device__ __forceinline__ uint32_t smem_u32(const void* p) {
    uint32_t a;
    asm("{ .reg .u64 t; cvta.to.shared.u64 t, %1; cvt.u32.u64 %0, t; }" : "=r"(a) : "l"(p));
    return a;
}
#define CP_ASYNC16(dst, src) \
    asm volatile("cp.async.cg.shared.global [%0], [%1], 16;" :: "r"(dst), "l"(src) : "memory")
#define CP_COMMIT() asm volatile("cp.async.commit_group;" ::: "memory")
#define CP_WAIT0()  asm volatile("cp.async.wait_group 0;" ::: "memory")
#define CP_WAIT1()  asm volatile("cp.async.wait_group 1;" ::: "memory")
#define LDSM4(r0,r1,r2,r3, addr) \
    asm volatile("ldmatrix.sync.aligned.m8n8.x4.shared.b16 {%0,%1,%2,%3}, [%4];" \
        : "=r"(r0), "=r"(r1), "=r"(r2), "=r"(r3) : "r"(addr))

__device__ __forceinline__ void mma16816(float* c, uint32_t a0, uint32_t a1, uint32_t a2,
                                         uint32_t a3, uint32_t b0, uint32_t b1) {
    asm volatile(
        "mma.sync.aligned.m16n8k16.row.col.f32.f16.f16.f32 "
        "{%0,%1,%2,%3}, {%4,%5,%6,%7}, {%8,%9}, {%0,%1,%2,%3};"
        : "+f"(c[0]), "+f"(c[1]), "+f"(c[2]), "+f"(c[3])
        : "r"(a0), "r"(a1), "r"(a2), "r"(a3), "r"(b0), "r"(b1));
}

// ---- staging: 32 rows x 64 k-halves (hi+lo), padded SMEM rows of 144B ----
__device__ __forceinline__ void stage32(uint32_t dst0, const __half* __restrict__ ghi,
                                        const __half* __restrict__ glo,
                                        int row0, int k0, int tid) {
    #pragma unroll
    for (int e = 0; e < 4; ++e) {                 // 2 part x 32 rows x 8 segs
        int idx = tid + e * NTHR;
        const __half* g = (e < 2) ? ghi : glo;
        uint32_t po = (e < 2) ? 0u : A_PART;
        int rem = idx & 255, r = rem >> 3, seg = rem & 7;
        CP_ASYNC16(dst0 + po + (uint32_t)(r * 144 + seg * 16),
                   g + (size_t)(row0 + r) * 512 + k0 + seg * 8);
    }
}

// one chunk: NKS k16-steps, warp tile m16 x n16, split-fp16 (6 mma / k16)
template<int NKS>
__device__ __forceinline__ void compute_chunk(
    uint32_t aBase, uint32_t aPart, uint32_t aStr,
    uint32_t bBase, uint32_t bPart, uint32_t bStr,
    int mw, int nw, int lane, float acc[2][4])
{
    const int m = lane >> 3, rr = lane & 7;
    const uint32_t aAddr = aBase + (uint32_t)(mw * 16 + (m & 1) * 8 + rr) * aStr
                         + (uint32_t)((m >> 1) * 16);
    const uint32_t bAddr = bBase + (uint32_t)(nw * 16 + (m >> 1) * 8 + rr) * bStr
                         + (uint32_t)((m & 1) * 16);
    #pragma unroll
    for (int ks = 0; ks < NKS; ++ks) {
        uint32_t ah0, ah1, ah2, ah3, al0, al1, al2, al3;
        LDSM4(ah0, ah1, ah2, ah3, aAddr + ks * 32);
        LDSM4(al0, al1, al2, al3, aAddr + aPart + ks * 32);
        uint32_t bh0, bh1, bh2, bh3, bl0, bl1, bl2, bl3;
        LDSM4(bh0, bh1, bh2, bh3, bAddr + ks * 32);
        LDSM4(bl0, bl1, bl2, bl3, bAddr + bPart + ks * 32);
        mma16816(acc[0], ah0, ah1, ah2, ah3, bh0, bh1);
        mma16816(acc[0], ah0, ah1, ah2, ah3, bl0, bl1);
        mma16816(acc[0], al0, al1, al2, al3, bh0, bh1);
        mma16816(acc[1], ah0, ah1, ah2, ah3, bh2, bh3);
        mma16816(acc[1], ah0, ah1, ah2, ah3, bl2, bl3);
        mma16816(acc[1], al0, al1, al2, al3, bh2, bh3);
    }
}

__device__ __forceinline__ void grid_barrier(unsigned gen) {
    __syncthreads();
    if (threadIdx.x == 0) {
        __threadfence();
        if (atomicAdd(&g_bar_count, 1u) == (unsigned)(NCTA - 1)) {
            g_bar_count = 0u;
            __threadfence();
            g_bar_gen = gen + 1u;
        } else {
            while (g_bar_gen == gen) { }
            __threadfence();
        }
    }
    __syncthreads();
}

__global__ void __launch_bounds__(NTHR, 2) coesn_mma(
    const float* __restrict__ x,    const float* __restrict__ x2h,
    const float* __restrict__ h2h,  const float* __restrict__ h2hT,
    const float* __restrict__ bias, const float* __restrict__ gamma,
    const float* __restrict__ eps,  float* __restrict__ out, int write_final)
{
    extern __shared__ __align__(16) char smem[];
    const uint32_t sb = smem_u32(smem);
    const int tid = threadIdx.x;
    const int w = tid >> 5, lane = tid & 31;
    const int mw = w & 1, nw = w >> 1;         // 2 m-warps x 2 n-warps
    const int bidx = blockIdx.x;
    const int b0 = (bidx >> 4) * 32;           // 16 b-tiles
    const int h0 = (bidx & 15) * 32;           // 16 h-tiles

    unsigned gen = g_bar_gen;

    // ---- cooperative init: split weights, zero hy ----
    const int gtid = bidx * NTHR + tid;        // 0..32767
    #pragma unroll 1
    for (int e = 0; e < 8; ++e) {
        int idx = gtid + e * (NCTA * NTHR);    // 0..262143
        int r = idx >> 9, c = idx & 511;
        float v1 = h2h[(size_t)c * Hq + r];    // W1[h=r][k=c] = h2h[k][h]
        __half h1 = __float2half_rn(v1);
        g_W1_hi[idx] = h1;
        g_W1_lo[idx] = __float2half_rn(v1 - __half2float(h1));
        float v2 = -h2hT[idx];                 // W2[b][j] = -h2hT[b][j]
        __half h2v = __float2half_rn(v2);
        g_W2_hi[idx] = h2v;
        g_W2_lo[idx] = __float2half_rn(v2 - __half2float(h2v));
        __half z = __float2half_rn(0.f);
        g_hy_hi[idx] = z;
        g_hy_lo[idx] = z;
    }
    // BX = x2h^T slice [32 h][32 i]
    #pragma unroll
    for (int e = 0; e < 16; ++e) {
        int idx = tid + e * NTHR;              // 0..2047
        int part = (idx >= 1024);
        int rem = idx & 1023, r = rem >> 5, ii = rem & 31;
        float v = x2h[(size_t)ii * Hq + h0 + r];
        __half hv = __float2half_rn(v);
        __half val = part ? __float2half_rn(v - __half2float(hv)) : hv;
        *(__half*)(smem + OFF_BX + part * BX_PART + r * 80 + ii * 2) = val;
    }
    if (tid < 32) {
        ((float*)(smem + OFF_SC))[tid]      = bias[h0 + tid];
        ((float*)(smem + OFF_SC))[32 + tid] = gamma[h0 + tid];
        ((float*)(smem + OFF_SC))[64 + tid] = eps[h0 + tid];
    }
    const float* scp = (const float*)(smem + OFF_SC);
    grid_barrier(gen); gen++;                  // weight splits visible chip-wide

    float hyr[2][4], hzr[2][4];
    #pragma unroll
    for (int p = 0; p < 2; ++p)
        #pragma unroll
        for (int j = 0; j < 4; ++j) { hyr[p][j] = 0.f; hzr[p][j] = 0.f; }

    #pragma unroll 1
    for (int t = 0; t < Lq; ++t) {
        // ===== Phase 1: D1 = hy @ h2h; T^T = tanh(D1 + bias)^T =====
        float acc[2][4];
        #pragma unroll
        for (int p = 0; p < 2; ++p)
            #pragma unroll
            for (int j = 0; j < 4; ++j) acc[p][j] = 0.f;

        stage32(sb + OFF_A,         g_hy_hi, g_hy_lo, b0, 0,  tid);
        stage32(sb + OFF_B,         g_W1_hi, g_W1_lo, h0, 0,  tid);
        CP_COMMIT();
        stage32(sb + OFF_A + A_BUF, g_hy_hi, g_hy_lo, b0, 64, tid);
        stage32(sb + OFF_B + A_BUF, g_W1_hi, g_W1_lo, h0, 64, tid);
        CP_COMMIT();
        #pragma unroll 1
        for (int kc = 0; kc < 8; ++kc) {
            if (kc < 7) { CP_WAIT1(); } else { CP_WAIT0(); }
            __syncthreads();
            if (kc + 2 < 8) {
                stage32(sb + OFF_A + (uint32_t)((kc + 2) % 3) * A_BUF,
                        g_hy_hi, g_hy_lo, b0, (kc + 2) * 64, tid);
                stage32(sb + OFF_B + (uint32_t)((kc + 2) % 3) * A_BUF,
                        g_W1_hi, g_W1_lo, h0, (kc + 2) * 64, tid);
                CP_COMMIT();
            }
            compute_chunk<4>(sb + OFF_A + (uint32_t)(kc % 3) * A_BUF, A_PART, 144u,
                             sb + OFF_B + (uint32_t)(kc % 3) * A_BUF, A_PART, 144u,
                             mw, nw, lane, acc);
        }

        // tanh + split -> T smem
        #pragma unroll
        for (int p = 0; p < 2; ++p) {
            #pragma unroll
            for (int j = 0; j < 4; ++j) {
                int hc = nw * 16 + p * 8 + 2 * (lane & 3) + (j & 1);
                int bl = mw * 16 + (lane >> 2) + ((j >> 1) * 8);
                float v = acc[p][j] + scp[hc];
                float e2 = __expf(2.f * v);
                float tv = 1.f - 2.f / (e2 + 1.f);
                __half hv = __float2half_rn(tv);
                __half lv = __float2half_rn(tv - __half2float(hv));
                *(__half*)(smem + OFF_T + hc * 80 + bl * 2) = hv;
                *(__half*)(smem + OFF_T + T_PART + hc * 80 + bl * 2) = lv;
            }
        }
        __syncthreads();
        #pragma unroll
        for (int e = 0; e < 2; ++e) {          // 2 part x 32 rows x 4 uint4
            int idx = tid + e * NTHR;
            int part = idx >> 7;
            int rem = idx & 127, r = rem >> 2, q = rem & 3;
            uint4 val = *(const uint4*)(smem + OFF_T + part * T_PART + r * 80 + q * 16);
            __half* g = part ? g_Tt_lo : g_Tt_hi;
            *(uint4*)(g + (size_t)(h0 + r) * 512 + b0 + q * 8) = val;
        }
        grid_barrier(gen); gen++;

        // ===== Phase 2: D2 = x_t @ x2h - h2hT @ T =====
        stage32(sb + OFF_A,         g_W2_hi, g_W2_lo, b0, 0,  tid);
        stage32(sb + OFF_B,         g_Tt_hi, g_Tt_lo, h0, 0,  tid);
        CP_COMMIT();
        stage32(sb + OFF_A + A_BUF, g_W2_hi, g_W2_lo, b0, 64, tid);
        stage32(sb + OFF_B + A_BUF, g_Tt_hi, g_Tt_lo, h0, 64, tid);
        CP_COMMIT();
        // x_t split -> X SMEM (visibility covered by kc=0 __syncthreads)
        #pragma unroll
        for (int e = 0; e < 2; ++e) {
            int idx = tid + e * NTHR;          // 0..255 = 32 rows x 8 float4-segs
            int r = idx >> 3, q = idx & 7;
            float4 v = *(const float4*)(x + (size_t)(b0 + r) * (Lq * Iq)
                                          + (size_t)t * Iq + q * 4);
            __half h0v = __float2half_rn(v.x), h1v = __float2half_rn(v.y);
            __half h2v = __float2half_rn(v.z), h3v = __float2half_rn(v.w);
            __half l0v = __float2half_rn(v.x - __half2float(h0v));
            __half l1v = __float2half_rn(v.y - __half2float(h1v));
            __half l2v = __float2half_rn(v.z - __half2float(h2v));
            __half l3v = __float2half_rn(v.w - __half2float(h3v));
            char* dh = smem + OFF_X + r * 80 + q * 8;
            char* dl = dh + X_PART;
            *(__half2*)(dh)     = __halves2half2(h0v, h1v);
            *(__half2*)(dh + 4) = __halves2half2(h2v, h3v);
            *(__half2*)(dl)     = __halves2half2(l0v, l1v);
            *(__half2*)(dl + 4) = __halves2half2(l2v, l3v);
        }
        #pragma unroll
        for (int p = 0; p < 2; ++p)
            #pragma unroll
            for (int j = 0; j < 4; ++j) acc[p][j] = 0.f;
        #pragma unroll 1
        for (int kc = 0; kc < 8; ++kc) {
            if (kc < 7) { CP_WAIT1(); } else { CP_WAIT0(); }
            __syncthreads();
            if (kc + 2 < 8) {
                stage32(sb + OFF_A + (uint32_t)((kc + 2) % 3) * A_BUF,
                        g_W2_hi, g_W2_lo, b0, (kc + 2) * 64, tid);
                stage32(sb + OFF_B + (uint32_t)((kc + 2) % 3) * A_BUF,
                        g_Tt_hi, g_Tt_lo, h0, (kc + 2) * 64, tid);
                CP_COMMIT();
            }
            if (kc == 0) {
                compute_chunk<2>(sb + OFF_X, X_PART, 80u,
                                 sb + OFF_BX, BX_PART, 80u, mw, nw, lane, acc);
            }
            compute_chunk<4>(sb + OFF_A + (uint32_t)(kc % 3) * A_BUF, A_PART, 144u,
                             sb + OFF_B + (uint32_t)(kc % 3) * A_BUF, A_PART, 144u,
                             mw, nw, lane, acc);
        }

        // integrate state; hy -> O smem tile (stride 144B)
        #pragma unroll
        for (int p = 0; p < 2; ++p) {
            #pragma unroll
            for (int j = 0; j < 4; ++j) {
                int hc = nw * 16 + p * 8 + 2 * (lane & 3) + (j & 1);
                int bl = mw * 16 + (lane >> 2) + ((j >> 1) * 8);
                float hy = hyr[p][j], hz = hzr[p][j];
                hz += DTF * (acc[p][j] - scp[32 + hc] * hy - scp[64 + hc] * hz);
                hy += DTF * hz;
                hzr[p][j] = hz; hyr[p][j] = hy;
                *(float*)(smem + OFF_O + bl * 144 + hc * 4) = hy;
            }
        }
        __syncthreads();
        #pragma unroll
        for (int e = 0; e < 2; ++e) {
            int idx = tid + e * NTHR;          // 0..255 = 32 rows x 8 float4
            int r = idx >> 3, q = idx & 7;
            float4 v = *(const float4*)(smem + OFF_O + r * 144 + q * 16);
            *(float4*)(out + (size_t)(b0 + r) * (Lq * Hq) + (size_t)t * Hq
                           + h0 + q * 4) = v;
            __half a0 = __float2half_rn(v.x), a1 = __float2half_rn(v.y);
            __half a2 = __float2half_rn(v.z), a3 = __float2half_rn(v.w);
            __half c0 = __float2half_rn(v.x - __half2float(a0));
            __half c1 = __float2half_rn(v.y - __half2float(a1));
            __half c2 = __float2half_rn(v.z - __half2float(a2));
            __half c3 = __float2half_rn(v.w - __half2float(a3));
            size_t o = (size_t)(b0 + r) * 512 + h0 + q * 4;
            *(__half2*)(g_hy_hi + o)     = __halves2half2(a0, a1);
            *(__half2*)(g_hy_hi + o + 2) = __halves2half2(a2, a3);
            *(__half2*)(g_hy_lo + o)     = __halves2half2(c0, c1);
            *(__half2*)(g_hy_lo + o + 2) = __halves2half2(c2, c3);
        }
        grid_barrier(gen); gen++;
    }

    // final hy (second output)
    if (write_final) {
        #pragma unroll
        for (int p = 0; p < 2; ++p) {
            #pragma unroll
            for (int j = 0; j < 4; ++j) {
                int hc = nw * 16 + p * 8 + 2 * (lane & 3) + (j & 1);
                int bl = mw * 16 + (lane >> 2) + ((j >> 1) * 8);
                out[(size_t)Bq * Lq * Hq + (size_t)(b0 + bl) * Hq + h0 + hc] = hyr[p][j];
            }
        }
    }
}

extern "C" void kernel_launch(void* const* d_in, const int* in_sizes, int n_in,
                              void* d_out, int out_size) {
    const float* x    = (const float*)d_in[0];
    const float* x2h  = (const float*)d_in[1];
    const float* h2h  = (const float*)d_in[2];
    const float* h2hT = (const float*)d_in[3];
    const float* bias = (const float*)d_in[4];
    const float* gam  = (const float*)d_in[5];
    const float* eps  = (const float*)d_in[6];
    (void)in_sizes; (void)n_in;

    cudaFuncSetAttribute(coesn_mma, cudaFuncAttributeMaxDynamicSharedMemorySize, SMEM_TOT);
    const int write_final = (out_size >= Bq * Lq * Hq + Bq * Hq) ? 1 : 0;
    coesn_mma<<<NCTA, NTHR, SMEM_TOT>>>(x, x2h, h2h, h2hT, bias, gam, eps,
                                        (float*)d_out, write_final);
}

// round 10
// speedup vs baseline: 1.7135x; 1.1172x over previous
#include <cuda_runtime.h>
#include <cuda_fp16.h>
#include <cstdint>

#define Bq 512
#define Hq 512
#define Lq 512
#define Iq 32
#define DTF 0.042f
#define NCTA 128
#define NTHR 256

// ---- SMEM layout (bytes) ----
#define OFF_A   0
#define OFF_B   104448
#define OFF_X   156672
#define OFF_BX  166912
#define OFF_T   172032
#define OFF_O   181248
#define OFF_SC  190464
#define SMEM_TOT 190848

#define A_PART  17408u
#define A_BUF   34816u
#define B_PART  8704u
#define B_BUF   17408u
#define X_PART  5120u
#define BX_PART 2560u
#define T_PART  4608u

// ---- persistent device state ----
__device__ __align__(256) __half g_hy_hi[Bq*Hq], g_hy_lo[Bq*Hq];
__device__ __align__(256) __half g_Tt_hi[Hq*Bq], g_Tt_lo[Hq*Bq];   // T^T: [h][b]
__device__ __align__(256) __half g_W1_hi[Hq*Hq], g_W1_lo[Hq*Hq];   // h2h^T: [h][k]
__device__ __align__(256) __half g_W2_hi[Hq*Hq], g_W2_lo[Hq*Hq];   // -h2hT: [b][j]
__device__ unsigned g_bar_count = 0u;
__device__ volatile unsigned g_bar_gen = 0u;

__device__ __forceinline__ uint32_t smem_u32(const void* p) {
    uint32_t a;
    asm("{ .reg .u64 t; cvta.to.shared.u64 t, %1; cvt.u32.u64 %0, t; }" : "=r"(a) : "l"(p));
    return a;
}
#define CP_ASYNC16(dst, src) \
    asm volatile("cp.async.cg.shared.global [%0], [%1], 16;" :: "r"(dst), "l"(src) : "memory")
#define CP_COMMIT() asm volatile("cp.async.commit_group;" ::: "memory")
#define CP_WAIT0()  asm volatile("cp.async.wait_group 0;" ::: "memory")
#define CP_WAIT1()  asm volatile("cp.async.wait_group 1;" ::: "memory")
#define LDSM4(r0,r1,r2,r3, addr) \
    asm volatile("ldmatrix.sync.aligned.m8n8.x4.shared.b16 {%0,%1,%2,%3}, [%4];" \
        : "=r"(r0), "=r"(r1), "=r"(r2), "=r"(r3) : "r"(addr))

__device__ __forceinline__ void mma16816(float* c, uint32_t a0, uint32_t a1, uint32_t a2,
                                         uint32_t a3, uint32_t b0, uint32_t b1) {
    asm volatile(
        "mma.sync.aligned.m16n8k16.row.col.f32.f16.f16.f32 "
        "{%0,%1,%2,%3}, {%4,%5,%6,%7}, {%8,%9}, {%0,%1,%2,%3};"
        : "+f"(c[0]), "+f"(c[1]), "+f"(c[2]), "+f"(c[3])
        : "r"(a0), "r"(a1), "r"(a2), "r"(a3), "r"(b0), "r"(b1));
}

// ---- staging: BK=128, padded SMEM rows of 272B ----
__device__ __forceinline__ void stageA128(uint32_t dst0, const __half* __restrict__ ghi,
                                          const __half* __restrict__ glo,
                                          int row0, int k0, int tid) {
    #pragma unroll
    for (int e = 0; e < 8; ++e) {
        int idx = tid + e * NTHR;
        const __half* g = (e < 4) ? ghi : glo;
        uint32_t po = (e < 4) ? 0u : A_PART;
        int rem = idx & 1023, r = rem >> 4, seg = rem & 15;
        CP_ASYNC16(dst0 + po + (uint32_t)(r * 272 + seg * 16),
                   g + (size_t)(row0 + r) * 512 + k0 + seg * 8);
    }
}
__device__ __forceinline__ void stageB128(uint32_t dst0, const __half* __restrict__ ghi,
                                          const __half* __restrict__ glo,
                                          int row0, int k0, int tid) {
    #pragma unroll
    for (int e = 0; e < 4; ++e) {
        int idx = tid + e * NTHR;
        const __half* g = (e < 2) ? ghi : glo;
        uint32_t po = (e < 2) ? 0u : B_PART;
        int rem = idx & 511, r = rem >> 4, seg = rem & 15;
        CP_ASYNC16(dst0 + po + (uint32_t)(r * 272 + seg * 16),
                   g + (size_t)(row0 + r) * 512 + k0 + seg * 8);
    }
}

// one chunk: NKS k16-steps; 3 independent accumulator sets (HH, HL, LH)
// chain depth per acc = NKS (vs 3*NKS when fused) -> latency hiding
template<int NKS>
__device__ __forceinline__ void compute_chunk(
    uint32_t aBase, uint32_t aPart, uint32_t aStr,
    uint32_t bBase, uint32_t bPart, uint32_t bStr,
    int mw, int nw, int lane,
    float aHH[2][4], float aHL[2][4], float aLH[2][4])
{
    const int m = lane >> 3, rr = lane & 7;
    const uint32_t aAddr = aBase + (uint32_t)(mw * 16 + (m & 1) * 8 + rr) * aStr
                         + (uint32_t)((m >> 1) * 16);
    const uint32_t bAddr = bBase + (uint32_t)(nw * 16 + (m >> 1) * 8 + rr) * bStr
                         + (uint32_t)((m & 1) * 16);
    #pragma unroll
    for (int ks = 0; ks < NKS; ++ks) {
        uint32_t ah0, ah1, ah2, ah3, al0, al1, al2, al3;
        LDSM4(ah0, ah1, ah2, ah3, aAddr + ks * 32);
        LDSM4(al0, al1, al2, al3, aAddr + aPart + ks * 32);
        uint32_t bh0, bh1, bh2, bh3, bl0, bl1, bl2, bl3;
        LDSM4(bh0, bh1, bh2, bh3, bAddr + ks * 32);
        LDSM4(bl0, bl1, bl2, bl3, bAddr + bPart + ks * 32);
        mma16816(aHH[0], ah0, ah1, ah2, ah3, bh0, bh1);
        mma16816(aHL[0], ah0, ah1, ah2, ah3, bl0, bl1);
        mma16816(aLH[0], al0, al1, al2, al3, bh0, bh1);
        mma16816(aHH[1], ah0, ah1, ah2, ah3, bh2, bh3);
        mma16816(aHL[1], ah0, ah1, ah2, ah3, bl2, bl3);
        mma16816(aLH[1], al0, al1, al2, al3, bh2, bh3);
    }
}

__device__ __forceinline__ void grid_barrier(unsigned gen) {
    __syncthreads();
    if (threadIdx.x == 0) {
        __threadfence();
        if (atomicAdd(&g_bar_count, 1u) == (unsigned)(NCTA - 1)) {
            g_bar_count = 0u;
            __threadfence();
            g_bar_gen = gen + 1u;
        } else {
            while (g_bar_gen == gen) { }
            __threadfence();
        }
    }
    __syncthreads();
}

__global__ void __launch_bounds__(NTHR, 1) coesn_mma(
    const float* __restrict__ x,    const float* __restrict__ x2h,
    const float* __restrict__ h2h,  const float* __restrict__ h2hT,
    const float* __restrict__ bias, const float* __restrict__ gamma,
    const float* __restrict__ eps,  float* __restrict__ out, int write_final)
{
    extern __shared__ __align__(16) char smem[];
    const uint32_t sb = smem_u32(smem);
    const int tid = threadIdx.x;
    const int w = tid >> 5, lane = tid & 31;
    const int mw = w & 3, nw = w >> 2;
    const int bidx = blockIdx.x;
    const int b0 = (bidx >> 4) * 64;
    const int h0 = (bidx & 15) * 32;

    unsigned gen = g_bar_gen;

    // ---- cooperative init ----
    const int gtid = bidx * NTHR + tid;
    #pragma unroll 1
    for (int e = 0; e < 8; ++e) {
        int idx = gtid + e * (NCTA * NTHR);
        int r = idx >> 9, c = idx & 511;
        float v1 = h2h[(size_t)c * Hq + r];
        __half h1 = __float2half_rn(v1);
        g_W1_hi[idx] = h1;
        g_W1_lo[idx] = __float2half_rn(v1 - __half2float(h1));
        float v2 = -h2hT[idx];
        __half h2v = __float2half_rn(v2);
        g_W2_hi[idx] = h2v;
        g_W2_lo[idx] = __float2half_rn(v2 - __half2float(h2v));
        __half z = __float2half_rn(0.f);
        g_hy_hi[idx] = z;
        g_hy_lo[idx] = z;
    }
    #pragma unroll
    for (int e = 0; e < 8; ++e) {
        int idx = tid + e * NTHR;
        int part = (idx >= 1024);
        int rem = idx & 1023, r = rem >> 5, ii = rem & 31;
        float v = x2h[(size_t)ii * Hq + h0 + r];
        __half hv = __float2half_rn(v);
        __half val = part ? __float2half_rn(v - __half2float(hv)) : hv;
        *(__half*)(smem + OFF_BX + part * BX_PART + r * 80 + ii * 2) = val;
    }
    if (tid < 32) {
        ((float*)(smem + OFF_SC))[tid]      = bias[h0 + tid];
        ((float*)(smem + OFF_SC))[32 + tid] = gamma[h0 + tid];
        ((float*)(smem + OFF_SC))[64 + tid] = eps[h0 + tid];
    }
    const float* scp = (const float*)(smem + OFF_SC);
    grid_barrier(gen); gen++;

    // pre-stage static W1 chunk0 for the first phase-1
    stageB128(sb + OFF_B, g_W1_hi, g_W1_lo, h0, 0, tid);
    CP_COMMIT();

    float hyr[2][4], hzr[2][4];
    #pragma unroll
    for (int p = 0; p < 2; ++p)
        #pragma unroll
        for (int j = 0; j < 4; ++j) { hyr[p][j] = 0.f; hzr[p][j] = 0.f; }

    #pragma unroll 1
    for (int t = 0; t < Lq; ++t) {
        // ===== Phase 1: D1 = hy @ h2h; T^T = tanh(D1 + bias)^T =====
        float aHH[2][4], aHL[2][4], aLH[2][4];
        #pragma unroll
        for (int p = 0; p < 2; ++p)
            #pragma unroll
            for (int j = 0; j < 4; ++j) { aHH[p][j] = 0.f; aHL[p][j] = 0.f; aLH[p][j] = 0.f; }

        // W1 chunk0 already committed pre-barrier; stage dynamic hy chunk0 + chunk1 pair
        stageA128(sb + OFF_A, g_hy_hi, g_hy_lo, b0, 0, tid);
        CP_COMMIT();
        stageA128(sb + OFF_A + A_BUF, g_hy_hi, g_hy_lo, b0, 128, tid);
        stageB128(sb + OFF_B + B_BUF, g_W1_hi, g_W1_lo, h0, 128, tid);
        CP_COMMIT();
        #pragma unroll 1
        for (int kc = 0; kc < 4; ++kc) {
            if (kc < 3) { CP_WAIT1(); } else { CP_WAIT0(); }
            __syncthreads();
            if (kc + 2 < 4) {
                stageA128(sb + OFF_A + (uint32_t)((kc + 2) % 3) * A_BUF,
                          g_hy_hi, g_hy_lo, b0, (kc + 2) * 128, tid);
                stageB128(sb + OFF_B + (uint32_t)((kc + 2) % 3) * B_BUF,
                          g_W1_hi, g_W1_lo, h0, (kc + 2) * 128, tid);
                CP_COMMIT();
            }
            compute_chunk<8>(sb + OFF_A + (uint32_t)(kc % 3) * A_BUF, A_PART, 272u,
                             sb + OFF_B + (uint32_t)(kc % 3) * B_BUF, B_PART, 272u,
                             mw, nw, lane, aHH, aHL, aLH);
        }

        // tanh + split -> T smem
        #pragma unroll
        for (int p = 0; p < 2; ++p) {
            #pragma unroll
            for (int j = 0; j < 4; ++j) {
                int hc = nw * 16 + p * 8 + 2 * (lane & 3) + (j & 1);
                int bl = mw * 16 + (lane >> 2) + ((j >> 1) * 8);
                float v = aHH[p][j] + (aHL[p][j] + aLH[p][j]) + scp[hc];
                float e2 = __expf(2.f * v);
                float tv = 1.f - 2.f / (e2 + 1.f);
                __half hv = __float2half_rn(tv);
                __half lv = __float2half_rn(tv - __half2float(hv));
                *(__half*)(smem + OFF_T + hc * 144 + bl * 2) = hv;
                *(__half*)(smem + OFF_T + T_PART + hc * 144 + bl * 2) = lv;
            }
        }
        __syncthreads();
        // T -> global, plus pre-stage static W2 chunk0 (A-buf0 free after sync)
        stageA128(sb + OFF_A, g_W2_hi, g_W2_lo, b0, 0, tid);
        CP_COMMIT();
        #pragma unroll
        for (int e = 0; e < 2; ++e) {
            int idx = tid + e * NTHR;
            int part = idx >> 8;
            int rem = idx & 255, r = rem >> 3, q = rem & 7;
            uint4 val = *(const uint4*)(smem + OFF_T + part * T_PART + r * 144 + q * 16);
            __half* g = part ? g_Tt_lo : g_Tt_hi;
            *(uint4*)(g + (size_t)(h0 + r) * 512 + b0 + q * 8) = val;
        }
        grid_barrier(gen); gen++;

        // ===== Phase 2: D2 = x_t @ x2h - h2hT @ T =====
        stageB128(sb + OFF_B, g_Tt_hi, g_Tt_lo, h0, 0, tid);
        CP_COMMIT();
        stageA128(sb + OFF_A + A_BUF, g_W2_hi, g_W2_lo, b0, 128, tid);
        stageB128(sb + OFF_B + B_BUF, g_Tt_hi, g_Tt_lo, h0, 128, tid);
        CP_COMMIT();
        // x_t split -> X SMEM (visibility covered by kc=0 __syncthreads)
        #pragma unroll
        for (int e = 0; e < 2; ++e) {
            int idx = tid + e * NTHR;
            int r = idx >> 3, q = idx & 7;
            float4 v = *(const float4*)(x + (size_t)(b0 + r) * (Lq * Iq)
                                          + (size_t)t * Iq + q * 4);
            __half h0v = __float2half_rn(v.x), h1v = __float2half_rn(v.y);
            __half h2v = __float2half_rn(v.z), h3v = __float2half_rn(v.w);
            __half l0v = __float2half_rn(v.x - __half2float(h0v));
            __half l1v = __float2half_rn(v.y - __half2float(h1v));
            __half l2v = __float2half_rn(v.z - __half2float(h2v));
            __half l3v = __float2half_rn(v.w - __half2float(h3v));
            char* dh = smem + OFF_X + r * 80 + q * 8;
            char* dl = dh + X_PART;
            *(__half2*)(dh)     = __halves2half2(h0v, h1v);
            *(__half2*)(dh + 4) = __halves2half2(h2v, h3v);
            *(__half2*)(dl)     = __halves2half2(l0v, l1v);
            *(__half2*)(dl + 4) = __halves2half2(l2v, l3v);
        }
        #pragma unroll
        for (int p = 0; p < 2; ++p)
            #pragma unroll
            for (int j = 0; j < 4; ++j) { aHH[p][j] = 0.f; aHL[p][j] = 0.f; aLH[p][j] = 0.f; }
        #pragma unroll 1
        for (int kc = 0; kc < 4; ++kc) {
            if (kc < 3) { CP_WAIT1(); } else { CP_WAIT0(); }
            __syncthreads();
            if (kc + 2 < 4) {
                stageA128(sb + OFF_A + (uint32_t)((kc + 2) % 3) * A_BUF,
                          g_W2_hi, g_W2_lo, b0, (kc + 2) * 128, tid);
                stageB128(sb + OFF_B + (uint32_t)((kc + 2) % 3) * B_BUF,
                          g_Tt_hi, g_Tt_lo, h0, (kc + 2) * 128, tid);
                CP_COMMIT();
            }
            if (kc == 0) {
                compute_chunk<2>(sb + OFF_X, X_PART, 80u,
                                 sb + OFF_BX, BX_PART, 80u, mw, nw, lane,
                                 aHH, aHL, aLH);
            }
            compute_chunk<8>(sb + OFF_A + (uint32_t)(kc % 3) * A_BUF, A_PART, 272u,
                             sb + OFF_B + (uint32_t)(kc % 3) * B_BUF, B_PART, 272u,
                             mw, nw, lane, aHH, aHL, aLH);
        }

        // integrate; hy -> O smem tile
        #pragma unroll
        for (int p = 0; p < 2; ++p) {
            #pragma unroll
            for (int j = 0; j < 4; ++j) {
                int hc = nw * 16 + p * 8 + 2 * (lane & 3) + (j & 1);
                int bl = mw * 16 + (lane >> 2) + ((j >> 1) * 8);
                float acc = aHH[p][j] + (aHL[p][j] + aLH[p][j]);
                float hy = hyr[p][j], hz = hzr[p][j];
                hz += DTF * (acc - scp[32 + hc] * hy - scp[64 + hc] * hz);
                hy += DTF * hz;
                hzr[p][j] = hz; hyr[p][j] = hy;
                *(float*)(smem + OFF_O + bl * 144 + hc * 4) = hy;
            }
        }
        __syncthreads();
        // pre-stage static W1 chunk0 for next step (B-buf0 free after sync)
        if (t + 1 < Lq) {
            stageB128(sb + OFF_B, g_W1_hi, g_W1_lo, h0, 0, tid);
            CP_COMMIT();
        }
        #pragma unroll
        for (int e = 0; e < 2; ++e) {
            int idx = tid + e * NTHR;
            int r = idx >> 3, q = idx & 7;
            float4 v = *(const float4*)(smem + OFF_O + r * 144 + q * 16);
            *(float4*)(out + (size_t)(b0 + r) * (Lq * Hq) + (size_t)t * Hq
                           + h0 + q * 4) = v;
            __half a0 = __float2half_rn(v.x), a1 = __float2half_rn(v.y);
            __half a2 = __float2half_rn(v.z), a3 = __float2half_rn(v.w);
            __half c0 = __float2half_rn(v.x - __half2float(a0));
            __half c1 = __float2half_rn(v.y - __half2float(a1));
            __half c2 = __float2half_rn(v.z - __half2float(a2));
            __half c3 = __float2half_rn(v.w - __half2float(a3));
            size_t o = (size_t)(b0 + r) * 512 + h0 + q * 4;
            *(__half2*)(g_hy_hi + o)     = __halves2half2(a0, a1);
            *(__half2*)(g_hy_hi + o + 2) = __halves2half2(a2, a3);
            *(__half2*)(g_hy_lo + o)     = __halves2half2(c0, c1);
            *(__half2*)(g_hy_lo + o + 2) = __halves2half2(c2, c3);
        }
        grid_barrier(gen); gen++;
    }

    // final hy (second output)
    if (write_final) {
        #pragma unroll
        for (int p = 0; p < 2; ++p) {
            #pragma unroll
            for (int j = 0; j < 4; ++j) {
                int hc = nw * 16 + p * 8 + 2 * (lane & 3) + (j & 1);
                int bl = mw * 16 + (lane >> 2) + ((j >> 1) * 8);
                out[(size_t)Bq * Lq * Hq + (size_t)(b0 + bl) * Hq + h0 + hc] = hyr[p][j];
            }
        }
    }
}

extern "C" void kernel_launch(void* const* d_in, const int* in_sizes, int n_in,
                              void* d_out, int out_size) {
    const float* x    = (const float*)d_in[0];
    const float* x2h  = (const float*)d_in[1];
    const float* h2h  = (const float*)d_in[2];
    const float* h2hT = (const float*)d_in[3];
    const float* bias = (const float*)d_in[4];
    const float* gam  = (const float*)d_in[5];
    const float* eps  = (const float*)d_in[6];
    (void)in_sizes; (void)n_in;

    cudaFuncSetAttribute(coesn_mma, cudaFuncAttributeMaxDynamicSharedMemorySize, SMEM_TOT);
    const int write_final = (out_size >= Bq * Lq * Hq + Bq * Hq) ? 1 : 0;
    coesn_mma<<<NCTA, NTHR, SMEM_TOT>>>(x, x2h, h2h, h2hT, bias, gam, eps,
                                        (float*)d_out, write_final);
}

// round 11
// speedup vs baseline: 1.7885x; 1.0438x over previous
#include <cuda_runtime.h>
#include <cuda_fp16.h>
#include <cstdint>

#define Bq 512
#define Hq 512
#define Lq 512
#define Iq 32
#define DTF 0.042f
#define NCTA 128
#define NTHR 512

// ---- SMEM layout (bytes) ----
#define OFF_A   0
#define OFF_B   104448
#define OFF_X   156672
#define OFF_BX  166912
#define OFF_T   172032
#define OFF_O   181248
#define OFF_SC  190464
#define OFF_R   190848
#define SMEM_TOT 199040

#define A_PART  17408u
#define A_BUF   34816u
#define B_PART  8704u
#define B_BUF   17408u
#define X_PART  5120u
#define BX_PART 2560u
#define T_PART  4608u

// ---- persistent device state ----
__device__ __align__(256) __half g_hy_hi[Bq*Hq], g_hy_lo[Bq*Hq];
__device__ __align__(256) __half g_Tt_hi[Hq*Bq], g_Tt_lo[Hq*Bq];   // T^T: [h][b]
__device__ __align__(256) __half g_W1_hi[Hq*Hq], g_W1_lo[Hq*Hq];   // h2h^T: [h][k]
__device__ __align__(256) __half g_W2_hi[Hq*Hq], g_W2_lo[Hq*Hq];   // -h2hT: [b][j]
__device__ unsigned g_bar_count = 0u;
__device__ volatile unsigned g_bar_gen = 0u;

__device__ __forceinline__ uint32_t smem_u32(const void* p) {
    uint32_t a;
    asm("{ .reg .u64 t; cvta.to.shared.u64 t, %1; cvt.u32.u64 %0, t; }" : "=r"(a) : "l"(p));
    return a;
}
#define CP_ASYNC16(dst, src) \
    asm volatile("cp.async.cg.shared.global [%0], [%1], 16;" :: "r"(dst), "l"(src) : "memory")
#define CP_COMMIT() asm volatile("cp.async.commit_group;" ::: "memory")
#define CP_WAIT0()  asm volatile("cp.async.wait_group 0;" ::: "memory")
#define CP_WAIT1()  asm volatile("cp.async.wait_group 1;" ::: "memory")
#define LDSM4(r0,r1,r2,r3, addr) \
    asm volatile("ldmatrix.sync.aligned.m8n8.x4.shared.b16 {%0,%1,%2,%3}, [%4];" \
        : "=r"(r0), "=r"(r1), "=r"(r2), "=r"(r3) : "r"(addr))

__device__ __forceinline__ void mma16816(float* c, uint32_t a0, uint32_t a1, uint32_t a2,
                                         uint32_t a3, uint32_t b0, uint32_t b1) {
    asm volatile(
        "mma.sync.aligned.m16n8k16.row.col.f32.f16.f16.f32 "
        "{%0,%1,%2,%3}, {%4,%5,%6,%7}, {%8,%9}, {%0,%1,%2,%3};"
        : "+f"(c[0]), "+f"(c[1]), "+f"(c[2]), "+f"(c[3])
        : "r"(a0), "r"(a1), "r"(a2), "r"(a3), "r"(b0), "r"(b1));
}

// ---- staging: BK=128, padded SMEM rows of 272B (NTHR=512) ----
__device__ __forceinline__ void stageA128(uint32_t dst0, const __half* __restrict__ ghi,
                                          const __half* __restrict__ glo,
                                          int row0, int k0, int tid) {
    #pragma unroll
    for (int e = 0; e < 4; ++e) {                 // 2 part x 64 rows x 16 segs = 2048
        int idx = tid + e * NTHR;
        const __half* g = (e < 2) ? ghi : glo;
        uint32_t po = (e < 2) ? 0u : A_PART;
        int rem = idx & 1023, r = rem >> 4, seg = rem & 15;
        CP_ASYNC16(dst0 + po + (uint32_t)(r * 272 + seg * 16),
                   g + (size_t)(row0 + r) * 512 + k0 + seg * 8);
    }
}
__device__ __forceinline__ void stageB128(uint32_t dst0, const __half* __restrict__ ghi,
                                          const __half* __restrict__ glo,
                                          int row0, int k0, int tid) {
    #pragma unroll
    for (int e = 0; e < 2; ++e) {                 // 2 part x 32 rows x 16 segs = 1024
        int idx = tid + e * NTHR;
        const __half* g = (e < 1) ? ghi : glo;
        uint32_t po = (e < 1) ? 0u : B_PART;
        int rem = idx & 511, r = rem >> 4, seg = rem & 15;
        CP_ASYNC16(dst0 + po + (uint32_t)(r * 272 + seg * 16),
                   g + (size_t)(row0 + r) * 512 + k0 + seg * 8);
    }
}

// one chunk: NKSH k16-steps starting at ks0; warp tile m16 x n16; fused acc
template<int NKSH>
__device__ __forceinline__ void compute_chunk(
    uint32_t aBase, uint32_t aPart, uint32_t aStr,
    uint32_t bBase, uint32_t bPart, uint32_t bStr,
    int mw, int nw, int lane, int ks0, float acc[2][4])
{
    const int m = lane >> 3, rr = lane & 7;
    const uint32_t aAddr = aBase + (uint32_t)(mw * 16 + (m & 1) * 8 + rr) * aStr
                         + (uint32_t)((m >> 1) * 16) + (uint32_t)(ks0 * 32);
    const uint32_t bAddr = bBase + (uint32_t)(nw * 16 + (m >> 1) * 8 + rr) * bStr
                         + (uint32_t)((m & 1) * 16) + (uint32_t)(ks0 * 32);
    #pragma unroll
    for (int ks = 0; ks < NKSH; ++ks) {
        uint32_t ah0, ah1, ah2, ah3, al0, al1, al2, al3;
        LDSM4(ah0, ah1, ah2, ah3, aAddr + ks * 32);
        LDSM4(al0, al1, al2, al3, aAddr + aPart + ks * 32);
        uint32_t bh0, bh1, bh2, bh3, bl0, bl1, bl2, bl3;
        LDSM4(bh0, bh1, bh2, bh3, bAddr + ks * 32);
        LDSM4(bl0, bl1, bl2, bl3, bAddr + bPart + ks * 32);
        mma16816(acc[0], ah0, ah1, ah2, ah3, bh0, bh1);
        mma16816(acc[0], ah0, ah1, ah2, ah3, bl0, bl1);
        mma16816(acc[0], al0, al1, al2, al3, bh0, bh1);
        mma16816(acc[1], ah0, ah1, ah2, ah3, bh2, bh3);
        mma16816(acc[1], ah0, ah1, ah2, ah3, bl2, bl3);
        mma16816(acc[1], al0, al1, al2, al3, bh2, bh3);
    }
}

__device__ __forceinline__ void grid_barrier(unsigned gen) {
    __syncthreads();
    if (threadIdx.x == 0) {
        __threadfence();
        if (atomicAdd(&g_bar_count, 1u) == (unsigned)(NCTA - 1)) {
            g_bar_count = 0u;
            __threadfence();
            g_bar_gen = gen + 1u;
        } else {
            while (g_bar_gen == gen) { }
            __threadfence();
        }
    }
    __syncthreads();
}

// kseg reduction: kseg1 warps dump acc, kseg0 warps add. One sync inside.
__device__ __forceinline__ void kseg_reduce(uint32_t sb, int kseg, int mw, int nw,
                                            int lane, float acc[2][4]) {
    const uint32_t slot = sb + OFF_R + (uint32_t)(((mw * 2 + nw) * 32 + lane) * 32);
    if (kseg == 1) {
        *(float4*)(uintptr_t)0; // placeholder no-op removed by compiler
    }
    if (kseg == 1) {
        float4 v0 = make_float4(acc[0][0], acc[0][1], acc[0][2], acc[0][3]);
        float4 v1 = make_float4(acc[1][0], acc[1][1], acc[1][2], acc[1][3]);
        asm volatile("st.shared.v4.f32 [%0], {%1,%2,%3,%4};" ::
            "r"(slot), "f"(v0.x), "f"(v0.y), "f"(v0.z), "f"(v0.w) : "memory");
        asm volatile("st.shared.v4.f32 [%0], {%1,%2,%3,%4};" ::
            "r"(slot + 16), "f"(v1.x), "f"(v1.y), "f"(v1.z), "f"(v1.w) : "memory");
    }
    __syncthreads();
    if (kseg == 0) {
        float4 v0, v1;
        asm volatile("ld.shared.v4.f32 {%0,%1,%2,%3}, [%4];"
            : "=f"(v0.x), "=f"(v0.y), "=f"(v0.z), "=f"(v0.w) : "r"(slot));
        asm volatile("ld.shared.v4.f32 {%0,%1,%2,%3}, [%4];"
            : "=f"(v1.x), "=f"(v1.y), "=f"(v1.z), "=f"(v1.w) : "r"(slot + 16));
        acc[0][0] += v0.x; acc[0][1] += v0.y; acc[0][2] += v0.z; acc[0][3] += v0.w;
        acc[1][0] += v1.x; acc[1][1] += v1.y; acc[1][2] += v1.z; acc[1][3] += v1.w;
    }
}

__global__ void __launch_bounds__(NTHR, 1) coesn_mma(
    const float* __restrict__ x,    const float* __restrict__ x2h,
    const float* __restrict__ h2h,  const float* __restrict__ h2hT,
    const float* __restrict__ bias, const float* __restrict__ gamma,
    const float* __restrict__ eps,  float* __restrict__ out, int write_final)
{
    extern __shared__ __align__(16) char smem[];
    const uint32_t sb = smem_u32(smem);
    const int tid = threadIdx.x;
    const int w = tid >> 5, lane = tid & 31;
    const int mw = w & 3, nw = (w >> 2) & 1, kseg = w >> 3;   // 4 x 2 x 2 warps
    const int bidx = blockIdx.x;
    const int b0 = (bidx >> 4) * 64;
    const int h0 = (bidx & 15) * 32;

    unsigned gen = g_bar_gen;

    // ---- cooperative init ----
    const int gtid = bidx * NTHR + tid;          // 0..65535
    #pragma unroll 1
    for (int e = 0; e < 4; ++e) {
        int idx = gtid + e * (NCTA * NTHR);      // 0..262143
        int r = idx >> 9, c = idx & 511;
        float v1 = h2h[(size_t)c * Hq + r];
        __half h1 = __float2half_rn(v1);
        g_W1_hi[idx] = h1;
        g_W1_lo[idx] = __float2half_rn(v1 - __half2float(h1));
        float v2 = -h2hT[idx];
        __half h2v = __float2half_rn(v2);
        g_W2_hi[idx] = h2v;
        g_W2_lo[idx] = __float2half_rn(v2 - __half2float(h2v));
        __half z = __float2half_rn(0.f);
        g_hy_hi[idx] = z;
        g_hy_lo[idx] = z;
    }
    #pragma unroll
    for (int e = 0; e < 4; ++e) {
        int idx = tid + e * NTHR;                // 0..2047
        int part = (idx >= 1024);
        int rem = idx & 1023, r = rem >> 5, ii = rem & 31;
        float v = x2h[(size_t)ii * Hq + h0 + r];
        __half hv = __float2half_rn(v);
        __half val = part ? __float2half_rn(v - __half2float(hv)) : hv;
        *(__half*)(smem + OFF_BX + part * BX_PART + r * 80 + ii * 2) = val;
    }
    if (tid < 32) {
        ((float*)(smem + OFF_SC))[tid]      = bias[h0 + tid];
        ((float*)(smem + OFF_SC))[32 + tid] = gamma[h0 + tid];
        ((float*)(smem + OFF_SC))[64 + tid] = eps[h0 + tid];
    }
    const float* scp = (const float*)(smem + OFF_SC);
    grid_barrier(gen); gen++;

    // pre-stage static W1 chunk0 for the first phase-1
    stageB128(sb + OFF_B, g_W1_hi, g_W1_lo, h0, 0, tid);
    CP_COMMIT();

    float hyr[2][4], hzr[2][4];
    #pragma unroll
    for (int p = 0; p < 2; ++p)
        #pragma unroll
        for (int j = 0; j < 4; ++j) { hyr[p][j] = 0.f; hzr[p][j] = 0.f; }

    #pragma unroll 1
    for (int t = 0; t < Lq; ++t) {
        // ===== Phase 1: D1 = hy @ h2h; T^T = tanh(D1 + bias)^T =====
        float acc[2][4];
        #pragma unroll
        for (int p = 0; p < 2; ++p)
            #pragma unroll
            for (int j = 0; j < 4; ++j) acc[p][j] = 0.f;

        stageA128(sb + OFF_A, g_hy_hi, g_hy_lo, b0, 0, tid);
        CP_COMMIT();
        stageA128(sb + OFF_A + A_BUF, g_hy_hi, g_hy_lo, b0, 128, tid);
        stageB128(sb + OFF_B + B_BUF, g_W1_hi, g_W1_lo, h0, 128, tid);
        CP_COMMIT();
        #pragma unroll 1
        for (int kc = 0; kc < 4; ++kc) {
            if (kc < 3) { CP_WAIT1(); } else { CP_WAIT0(); }
            __syncthreads();
            if (kc + 2 < 4) {
                stageA128(sb + OFF_A + (uint32_t)((kc + 2) % 3) * A_BUF,
                          g_hy_hi, g_hy_lo, b0, (kc + 2) * 128, tid);
                stageB128(sb + OFF_B + (uint32_t)((kc + 2) % 3) * B_BUF,
                          g_W1_hi, g_W1_lo, h0, (kc + 2) * 128, tid);
                CP_COMMIT();
            }
            compute_chunk<4>(sb + OFF_A + (uint32_t)(kc % 3) * A_BUF, A_PART, 272u,
                             sb + OFF_B + (uint32_t)(kc % 3) * B_BUF, B_PART, 272u,
                             mw, nw, lane, kseg * 4, acc);
        }
        kseg_reduce(sb, kseg, mw, nw, lane, acc);

        // tanh + split -> T smem (kseg0 warps only)
        if (kseg == 0) {
            #pragma unroll
            for (int p = 0; p < 2; ++p) {
                #pragma unroll
                for (int j = 0; j < 4; ++j) {
                    int hc = nw * 16 + p * 8 + 2 * (lane & 3) + (j & 1);
                    int bl = mw * 16 + (lane >> 2) + ((j >> 1) * 8);
                    float v = acc[p][j] + scp[hc];
                    float e2 = __expf(2.f * v);
                    float tv = 1.f - 2.f / (e2 + 1.f);
                    __half hv = __float2half_rn(tv);
                    __half lv = __float2half_rn(tv - __half2float(hv));
                    *(__half*)(smem + OFF_T + hc * 144 + bl * 2) = hv;
                    *(__half*)(smem + OFF_T + T_PART + hc * 144 + bl * 2) = lv;
                }
            }
        }
        __syncthreads();
        // T -> global, plus pre-stage static W2 chunk0
        stageA128(sb + OFF_A, g_W2_hi, g_W2_lo, b0, 0, tid);
        CP_COMMIT();
        if (tid < 512) {                           // 2 part x 32 rows x 8 uint4
            int part = tid >> 8;
            int rem = tid & 255, r = rem >> 3, q = rem & 7;
            uint4 val = *(const uint4*)(smem + OFF_T + part * T_PART + r * 144 + q * 16);
            __half* g = part ? g_Tt_lo : g_Tt_hi;
            *(uint4*)(g + (size_t)(h0 + r) * 512 + b0 + q * 8) = val;
        }
        grid_barrier(gen); gen++;

        // ===== Phase 2: D2 = x_t @ x2h - h2hT @ T =====
        stageB128(sb + OFF_B, g_Tt_hi, g_Tt_lo, h0, 0, tid);
        CP_COMMIT();
        stageA128(sb + OFF_A + A_BUF, g_W2_hi, g_W2_lo, b0, 128, tid);
        stageB128(sb + OFF_B + B_BUF, g_Tt_hi, g_Tt_lo, h0, 128, tid);
        CP_COMMIT();
        // x_t split -> X SMEM (visibility covered by kc=0 __syncthreads)
        if (tid < 512) {                           // 64 rows x 8 float4-segs
            int r = tid >> 3, q = tid & 7;
            float4 v = *(const float4*)(x + (size_t)(b0 + r) * (Lq * Iq)
                                          + (size_t)t * Iq + q * 4);
            __half h0v = __float2half_rn(v.x), h1v = __float2half_rn(v.y);
            __half h2v = __float2half_rn(v.z), h3v = __float2half_rn(v.w);
            __half l0v = __float2half_rn(v.x - __half2float(h0v));
            __half l1v = __float2half_rn(v.y - __half2float(h1v));
            __half l2v = __float2half_rn(v.z - __half2float(h2v));
            __half l3v = __float2half_rn(v.w - __half2float(h3v));
            char* dh = smem + OFF_X + r * 80 + q * 8;
            char* dl = dh + X_PART;
            *(__half2*)(dh)     = __halves2half2(h0v, h1v);
            *(__half2*)(dh + 4) = __halves2half2(h2v, h3v);
            *(__half2*)(dl)     = __halves2half2(l0v, l1v);
            *(__half2*)(dl + 4) = __halves2half2(l2v, l3v);
        }
        #pragma unroll
        for (int p = 0; p < 2; ++p)
            #pragma unroll
            for (int j = 0; j < 4; ++j) acc[p][j] = 0.f;
        #pragma unroll 1
        for (int kc = 0; kc < 4; ++kc) {
            if (kc < 3) { CP_WAIT1(); } else { CP_WAIT0(); }
            __syncthreads();
            if (kc + 2 < 4) {
                stageA128(sb + OFF_A + (uint32_t)((kc + 2) % 3) * A_BUF,
                          g_W2_hi, g_W2_lo, b0, (kc + 2) * 128, tid);
                stageB128(sb + OFF_B + (uint32_t)((kc + 2) % 3) * B_BUF,
                          g_Tt_hi, g_Tt_lo, h0, (kc + 2) * 128, tid);
                CP_COMMIT();
            }
            if (kc == 0) {
                compute_chunk<1>(sb + OFF_X, X_PART, 80u,
                                 sb + OFF_BX, BX_PART, 80u, mw, nw, lane, kseg, acc);
            }
            compute_chunk<4>(sb + OFF_A + (uint32_t)(kc % 3) * A_BUF, A_PART, 272u,
                             sb + OFF_B + (uint32_t)(kc % 3) * B_BUF, B_PART, 272u,
                             mw, nw, lane, kseg * 4, acc);
        }
        kseg_reduce(sb, kseg, mw, nw, lane, acc);

        // integrate (kseg0); hy -> O smem tile
        if (kseg == 0) {
            #pragma unroll
            for (int p = 0; p < 2; ++p) {
                #pragma unroll
                for (int j = 0; j < 4; ++j) {
                    int hc = nw * 16 + p * 8 + 2 * (lane & 3) + (j & 1);
                    int bl = mw * 16 + (lane >> 2) + ((j >> 1) * 8);
                    float hy = hyr[p][j], hz = hzr[p][j];
                    hz += DTF * (acc[p][j] - scp[32 + hc] * hy - scp[64 + hc] * hz);
                    hy += DTF * hz;
                    hzr[p][j] = hz; hyr[p][j] = hy;
                    *(float*)(smem + OFF_O + bl * 144 + hc * 4) = hy;
                }
            }
        }
        __syncthreads();
        // pre-stage static W1 chunk0 for next step
        if (t + 1 < Lq) {
            stageB128(sb + OFF_B, g_W1_hi, g_W1_lo, h0, 0, tid);
            CP_COMMIT();
        }
        if (tid < 512) {                           // 64 rows x 8 float4
            int r = tid >> 3, q = tid & 7;
            float4 v = *(const float4*)(smem + OFF_O + r * 144 + q * 16);
            *(float4*)(out + (size_t)(b0 + r) * (Lq * Hq) + (size_t)t * Hq
                           + h0 + q * 4) = v;
            __half a0 = __float2half_rn(v.x), a1 = __float2half_rn(v.y);
            __half a2 = __float2half_rn(v.z), a3 = __float2half_rn(v.w);
            __half c0 = __float2half_rn(v.x - __half2float(a0));
            __half c1 = __float2half_rn(v.y - __half2float(a1));
            __half c2 = __float2half_rn(v.z - __half2float(a2));
            __half c3 = __float2half_rn(v.w - __half2float(a3));
            size_t o = (size_t)(b0 + r) * 512 + h0 + q * 4;
            *(__half2*)(g_hy_hi + o)     = __halves2half2(a0, a1);
            *(__half2*)(g_hy_hi + o + 2) = __halves2half2(a2, a3);
            *(__half2*)(g_hy_lo + o)     = __halves2half2(c0, c1);
            *(__half2*)(g_hy_lo + o + 2) = __halves2half2(c2, c3);
        }
        grid_barrier(gen); gen++;
    }

    // final hy (second output)
    if (write_final && kseg == 0) {
        #pragma unroll
        for (int p = 0; p < 2; ++p) {
            #pragma unroll
            for (int j = 0; j < 4; ++j) {
                int hc = nw * 16 + p * 8 + 2 * (lane & 3) + (j & 1);
                int bl = mw * 16 + (lane >> 2) + ((j >> 1) * 8);
                out[(size_t)Bq * Lq * Hq + (size_t)(b0 + bl) * Hq + h0 + hc] = hyr[p][j];
            }
        }
    }
}

extern "C" void kernel_launch(void* const* d_in, const int* in_sizes, int n_in,
                              void* d_out, int out_size) {
    const float* x    = (const float*)d_in[0];
    const float* x2h  = (const float*)d_in[1];
    const float* h2h  = (const float*)d_in[2];
    const float* h2hT = (const float*)d_in[3];
    const float* bias = (const float*)d_in[4];
    const float* gam  = (const float*)d_in[5];
    const float* eps  = (const float*)d_in[6];
    (void)in_sizes; (void)n_in;

    cudaFuncSetAttribute(coesn_mma, cudaFuncAttributeMaxDynamicSharedMemorySize, SMEM_TOT);
    const int write_final = (out_size >= Bq * Lq * Hq + Bq * Hq) ? 1 : 0;
    coesn_mma<<<NCTA, NTHR, SMEM_TOT>>>(x, x2h, h2h, h2hT, bias, gam, eps,
                                        (float*)d_out, write_final);
}

// round 12
// speedup vs baseline: 2.0550x; 1.1490x over previous
#include <cuda_runtime.h>
#include <cuda_fp16.h>
#include <cstdint>

#define Bq 512
#define Hq 512
#define Lq 512
#define Iq 32
#define DTF 0.042f
#define NCTA 128
#define NTHR 512

// ---- SMEM layout (bytes) ----
#define OFF_A   0
#define OFF_B   104448
#define OFF_X   156672
#define OFF_BX  166912
#define OFF_T   172032
#define OFF_O   181248
#define OFF_SC  190464
#define OFF_R   190848
#define SMEM_TOT 199040

#define A_PART  17408u
#define A_BUF   34816u
#define B_PART  8704u
#define B_BUF   17408u
#define BX_PART 2560u

// ---- persistent device state ----
__device__ __align__(256) __half g_hy_hi[Bq*Hq];                   // dyn: hi only
__device__ __align__(256) __half g_Tt_hi[Hq*Bq];                   // T^T [h][b]: hi only
__device__ __align__(256) __half g_W1_hi[Hq*Hq], g_W1_lo[Hq*Hq];   // h2h^T: [h][k] split
__device__ __align__(256) __half g_W2_hi[Hq*Hq], g_W2_lo[Hq*Hq];   // -h2hT: [b][j] split
__device__ unsigned g_bar_count = 0u;
__device__ volatile unsigned g_bar_gen = 0u;

__device__ __forceinline__ uint32_t smem_u32(const void* p) {
    uint32_t a;
    asm("{ .reg .u64 t; cvta.to.shared.u64 t, %1; cvt.u32.u64 %0, t; }" : "=r"(a) : "l"(p));
    return a;
}
#define CP_ASYNC16(dst, src) \
    asm volatile("cp.async.cg.shared.global [%0], [%1], 16;" :: "r"(dst), "l"(src) : "memory")
#define CP_COMMIT() asm volatile("cp.async.commit_group;" ::: "memory")
#define CP_WAIT0()  asm volatile("cp.async.wait_group 0;" ::: "memory")
#define CP_WAIT1()  asm volatile("cp.async.wait_group 1;" ::: "memory")
#define LDSM4(r0,r1,r2,r3, addr) \
    asm volatile("ldmatrix.sync.aligned.m8n8.x4.shared.b16 {%0,%1,%2,%3}, [%4];" \
        : "=r"(r0), "=r"(r1), "=r"(r2), "=r"(r3) : "r"(addr))

__device__ __forceinline__ void mma16816(float* c, uint32_t a0, uint32_t a1, uint32_t a2,
                                         uint32_t a3, uint32_t b0, uint32_t b1) {
    asm volatile(
        "mma.sync.aligned.m16n8k16.row.col.f32.f16.f16.f32 "
        "{%0,%1,%2,%3}, {%4,%5,%6,%7}, {%8,%9}, {%0,%1,%2,%3};"
        : "+f"(c[0]), "+f"(c[1]), "+f"(c[2]), "+f"(c[3])
        : "r"(a0), "r"(a1), "r"(a2), "r"(a3), "r"(b0), "r"(b1));
}

// ---- staging (BK=128, padded rows of 272B; NTHR=512) ----
__device__ __forceinline__ void stageA_hi(uint32_t dst0, const __half* __restrict__ ghi,
                                          int row0, int k0, int tid) {
    #pragma unroll
    for (int e = 0; e < 2; ++e) {                 // 64 rows x 16 segs = 1024
        int idx = tid + e * NTHR;
        int rem = idx & 1023, r = rem >> 4, seg = rem & 15;
        CP_ASYNC16(dst0 + (uint32_t)(r * 272 + seg * 16),
                   ghi + (size_t)(row0 + r) * 512 + k0 + seg * 8);
    }
}
__device__ __forceinline__ void stageA_sp(uint32_t dst0, const __half* __restrict__ ghi,
                                          const __half* __restrict__ glo,
                                          int row0, int k0, int tid) {
    #pragma unroll
    for (int e = 0; e < 4; ++e) {                 // 2 part x 64 rows x 16 segs
        int idx = tid + e * NTHR;
        const __half* g = (e < 2) ? ghi : glo;
        uint32_t po = (e < 2) ? 0u : A_PART;
        int rem = idx & 1023, r = rem >> 4, seg = rem & 15;
        CP_ASYNC16(dst0 + po + (uint32_t)(r * 272 + seg * 16),
                   g + (size_t)(row0 + r) * 512 + k0 + seg * 8);
    }
}
__device__ __forceinline__ void stageB_hi(uint32_t dst0, const __half* __restrict__ ghi,
                                          int row0, int k0, int tid) {
    int r = tid >> 4, seg = tid & 15;             // 32 rows x 16 segs = 512
    CP_ASYNC16(dst0 + (uint32_t)(r * 272 + seg * 16),
               ghi + (size_t)(row0 + r) * 512 + k0 + seg * 8);
}
__device__ __forceinline__ void stageB_sp(uint32_t dst0, const __half* __restrict__ ghi,
                                          const __half* __restrict__ glo,
                                          int row0, int k0, int tid) {
    #pragma unroll
    for (int e = 0; e < 2; ++e) {                 // 2 part x 32 rows x 16 segs
        int idx = tid + e * NTHR;
        const __half* g = (e < 1) ? ghi : glo;
        uint32_t po = (e < 1) ? 0u : B_PART;
        int rem = idx & 511, r = rem >> 4, seg = rem & 15;
        CP_ASYNC16(dst0 + po + (uint32_t)(r * 272 + seg * 16),
                   g + (size_t)(row0 + r) * 512 + k0 + seg * 8);
    }
}

// chunk with B split (A hi-only): 2 MMAs per n16 per k-step
template<int NKSH>
__device__ __forceinline__ void chunk_Bsplit(
    uint32_t aBase, uint32_t aStr,
    uint32_t bBase, uint32_t bPart, uint32_t bStr,
    int mw, int nw, int lane, int ks0, float acc[2][4])
{
    const int m = lane >> 3, rr = lane & 7;
    const uint32_t aAddr = aBase + (uint32_t)(mw * 16 + (m & 1) * 8 + rr) * aStr
                         + (uint32_t)((m >> 1) * 16) + (uint32_t)(ks0 * 32);
    const uint32_t bAddr = bBase + (uint32_t)(nw * 16 + (m >> 1) * 8 + rr) * bStr
                         + (uint32_t)((m & 1) * 16) + (uint32_t)(ks0 * 32);
    #pragma unroll
    for (int ks = 0; ks < NKSH; ++ks) {
        uint32_t ah0, ah1, ah2, ah3;
        LDSM4(ah0, ah1, ah2, ah3, aAddr + ks * 32);
        uint32_t bh0, bh1, bh2, bh3, bl0, bl1, bl2, bl3;
        LDSM4(bh0, bh1, bh2, bh3, bAddr + ks * 32);
        LDSM4(bl0, bl1, bl2, bl3, bAddr + bPart + ks * 32);
        mma16816(acc[0], ah0, ah1, ah2, ah3, bh0, bh1);
        mma16816(acc[0], ah0, ah1, ah2, ah3, bl0, bl1);
        mma16816(acc[1], ah0, ah1, ah2, ah3, bh2, bh3);
        mma16816(acc[1], ah0, ah1, ah2, ah3, bl2, bl3);
    }
}
// chunk with A split (B hi-only)
template<int NKSH>
__device__ __forceinline__ void chunk_Asplit(
    uint32_t aBase, uint32_t aPart, uint32_t aStr,
    uint32_t bBase, uint32_t bStr,
    int mw, int nw, int lane, int ks0, float acc[2][4])
{
    const int m = lane >> 3, rr = lane & 7;
    const uint32_t aAddr = aBase + (uint32_t)(mw * 16 + (m & 1) * 8 + rr) * aStr
                         + (uint32_t)((m >> 1) * 16) + (uint32_t)(ks0 * 32);
    const uint32_t bAddr = bBase + (uint32_t)(nw * 16 + (m >> 1) * 8 + rr) * bStr
                         + (uint32_t)((m & 1) * 16) + (uint32_t)(ks0 * 32);
    #pragma unroll
    for (int ks = 0; ks < NKSH; ++ks) {
        uint32_t ah0, ah1, ah2, ah3, al0, al1, al2, al3;
        LDSM4(ah0, ah1, ah2, ah3, aAddr + ks * 32);
        LDSM4(al0, al1, al2, al3, aAddr + aPart + ks * 32);
        uint32_t bh0, bh1, bh2, bh3;
        LDSM4(bh0, bh1, bh2, bh3, bAddr + ks * 32);
        mma16816(acc[0], ah0, ah1, ah2, ah3, bh0, bh1);
        mma16816(acc[0], al0, al1, al2, al3, bh0, bh1);
        mma16816(acc[1], ah0, ah1, ah2, ah3, bh2, bh3);
        mma16816(acc[1], al0, al1, al2, al3, bh2, bh3);
    }
}

__device__ __forceinline__ void grid_barrier(unsigned gen) {
    __syncthreads();
    if (threadIdx.x == 0) {
        __threadfence();
        if (atomicAdd(&g_bar_count, 1u) == (unsigned)(NCTA - 1)) {
            g_bar_count = 0u;
            __threadfence();
            g_bar_gen = gen + 1u;
        } else {
            while (g_bar_gen == gen) { }
            __threadfence();
        }
    }
    __syncthreads();
}

// kseg reduction: kseg1 warps dump acc, kseg0 warps add.
__device__ __forceinline__ void kseg_reduce(uint32_t sb, int kseg, int mw, int nw,
                                            int lane, float acc[2][4]) {
    const uint32_t slot = sb + OFF_R + (uint32_t)(((mw * 2 + nw) * 32 + lane) * 32);
    if (kseg == 1) {
        asm volatile("st.shared.v4.f32 [%0], {%1,%2,%3,%4};" ::
            "r"(slot), "f"(acc[0][0]), "f"(acc[0][1]), "f"(acc[0][2]), "f"(acc[0][3]) : "memory");
        asm volatile("st.shared.v4.f32 [%0], {%1,%2,%3,%4};" ::
            "r"(slot + 16), "f"(acc[1][0]), "f"(acc[1][1]), "f"(acc[1][2]), "f"(acc[1][3]) : "memory");
    }
    __syncthreads();
    if (kseg == 0) {
        float4 v0, v1;
        asm volatile("ld.shared.v4.f32 {%0,%1,%2,%3}, [%4];"
            : "=f"(v0.x), "=f"(v0.y), "=f"(v0.z), "=f"(v0.w) : "r"(slot));
        asm volatile("ld.shared.v4.f32 {%0,%1,%2,%3}, [%4];"
            : "=f"(v1.x), "=f"(v1.y), "=f"(v1.z), "=f"(v1.w) : "r"(slot + 16));
        acc[0][0] += v0.x; acc[0][1] += v0.y; acc[0][2] += v0.z; acc[0][3] += v0.w;
        acc[1][0] += v1.x; acc[1][1] += v1.y; acc[1][2] += v1.z; acc[1][3] += v1.w;
    }
}

__global__ void __launch_bounds__(NTHR, 1) coesn_mma(
    const float* __restrict__ x,    const float* __restrict__ x2h,
    const float* __restrict__ h2h,  const float* __restrict__ h2hT,
    const float* __restrict__ bias, const float* __restrict__ gamma,
    const float* __restrict__ eps,  float* __restrict__ out, int write_final)
{
    extern __shared__ __align__(16) char smem[];
    const uint32_t sb = smem_u32(smem);
    const int tid = threadIdx.x;
    const int w = tid >> 5, lane = tid & 31;
    const int mw = w & 3, nw = (w >> 2) & 1, kseg = w >> 3;
    const int bidx = blockIdx.x;
    const int b0 = (bidx >> 4) * 64;
    const int h0 = (bidx & 15) * 32;

    unsigned gen = g_bar_gen;

    // ---- cooperative init ----
    const int gtid = bidx * NTHR + tid;
    #pragma unroll 1
    for (int e = 0; e < 4; ++e) {
        int idx = gtid + e * (NCTA * NTHR);
        int r = idx >> 9, c = idx & 511;
        float v1 = h2h[(size_t)c * Hq + r];
        __half h1 = __float2half_rn(v1);
        g_W1_hi[idx] = h1;
        g_W1_lo[idx] = __float2half_rn(v1 - __half2float(h1));
        float v2 = -h2hT[idx];
        __half h2v = __float2half_rn(v2);
        g_W2_hi[idx] = h2v;
        g_W2_lo[idx] = __float2half_rn(v2 - __half2float(h2v));
        g_hy_hi[idx] = __float2half_rn(0.f);
    }
    #pragma unroll
    for (int e = 0; e < 4; ++e) {
        int idx = tid + e * NTHR;                // BX: 2 part x 32 h x 32 i
        int part = (idx >= 1024);
        int rem = idx & 1023, r = rem >> 5, ii = rem & 31;
        float v = x2h[(size_t)ii * Hq + h0 + r];
        __half hv = __float2half_rn(v);
        __half val = part ? __float2half_rn(v - __half2float(hv)) : hv;
        *(__half*)(smem + OFF_BX + part * BX_PART + r * 80 + ii * 2) = val;
    }
    if (tid < 32) {
        ((float*)(smem + OFF_SC))[tid]      = bias[h0 + tid];
        ((float*)(smem + OFF_SC))[32 + tid] = gamma[h0 + tid];
        ((float*)(smem + OFF_SC))[64 + tid] = eps[h0 + tid];
    }
    const float* scp = (const float*)(smem + OFF_SC);
    grid_barrier(gen); gen++;

    // pre-stage static W1 chunk0 (split) for the first phase-1
    stageB_sp(sb + OFF_B, g_W1_hi, g_W1_lo, h0, 0, tid);
    CP_COMMIT();

    float hyr[2][4], hzr[2][4];
    #pragma unroll
    for (int p = 0; p < 2; ++p)
        #pragma unroll
        for (int j = 0; j < 4; ++j) { hyr[p][j] = 0.f; hzr[p][j] = 0.f; }

    #pragma unroll 1
    for (int t = 0; t < Lq; ++t) {
        // ===== Phase 1: D1 = hy @ h2h (A=hy hi, B=W1 split) =====
        float acc[2][4];
        #pragma unroll
        for (int p = 0; p < 2; ++p)
            #pragma unroll
            for (int j = 0; j < 4; ++j) acc[p][j] = 0.f;

        stageA_hi(sb + OFF_A, g_hy_hi, b0, 0, tid);
        CP_COMMIT();
        stageA_hi(sb + OFF_A + A_BUF, g_hy_hi, b0, 128, tid);
        stageB_sp(sb + OFF_B + B_BUF, g_W1_hi, g_W1_lo, h0, 128, tid);
        CP_COMMIT();
        #pragma unroll 1
        for (int kc = 0; kc < 4; ++kc) {
            if (kc < 3) { CP_WAIT1(); } else { CP_WAIT0(); }
            __syncthreads();
            if (kc + 2 < 4) {
                stageA_hi(sb + OFF_A + (uint32_t)((kc + 2) % 3) * A_BUF,
                          g_hy_hi, b0, (kc + 2) * 128, tid);
                stageB_sp(sb + OFF_B + (uint32_t)((kc + 2) % 3) * B_BUF,
                          g_W1_hi, g_W1_lo, h0, (kc + 2) * 128, tid);
                CP_COMMIT();
            }
            chunk_Bsplit<4>(sb + OFF_A + (uint32_t)(kc % 3) * A_BUF, 272u,
                            sb + OFF_B + (uint32_t)(kc % 3) * B_BUF, B_PART, 272u,
                            mw, nw, lane, kseg * 4, acc);
        }
        kseg_reduce(sb, kseg, mw, nw, lane, acc);

        // tanh -> T smem (hi only; kseg0 warps)
        if (kseg == 0) {
            #pragma unroll
            for (int p = 0; p < 2; ++p) {
                #pragma unroll
                for (int j = 0; j < 4; ++j) {
                    int hc = nw * 16 + p * 8 + 2 * (lane & 3) + (j & 1);
                    int bl = mw * 16 + (lane >> 2) + ((j >> 1) * 8);
                    float v = acc[p][j] + scp[hc];
                    float e2 = __expf(2.f * v);
                    float tv = 1.f - 2.f / (e2 + 1.f);
                    *(__half*)(smem + OFF_T + hc * 144 + bl * 2) = __float2half_rn(tv);
                }
            }
        }
        __syncthreads();
        // T -> global; pre-stage static W2 chunk0 (split A)
        stageA_sp(sb + OFF_A, g_W2_hi, g_W2_lo, b0, 0, tid);
        CP_COMMIT();
        if (tid < 256) {                           // 32 rows x 8 uint4
            int r = tid >> 3, q = tid & 7;
            uint4 val = *(const uint4*)(smem + OFF_T + r * 144 + q * 16);
            *(uint4*)(g_Tt_hi + (size_t)(h0 + r) * 512 + b0 + q * 8) = val;
        }
        grid_barrier(gen); gen++;

        // ===== Phase 2: D2 = x_t @ x2h - h2hT @ T (A=W2 split, B=Tt hi) =====
        stageB_hi(sb + OFF_B, g_Tt_hi, h0, 0, tid);
        CP_COMMIT();
        stageA_sp(sb + OFF_A + A_BUF, g_W2_hi, g_W2_lo, b0, 128, tid);
        stageB_hi(sb + OFF_B + B_BUF, g_Tt_hi, h0, 128, tid);
        CP_COMMIT();
        // x_t (hi only) -> X SMEM; visibility via kc=0 __syncthreads
        {
            int r = tid >> 3, q = tid & 7;         // 64 rows x 8 float4-segs
            float4 v = *(const float4*)(x + (size_t)(b0 + r) * (Lq * Iq)
                                          + (size_t)t * Iq + q * 4);
            char* dh = smem + OFF_X + r * 80 + q * 8;
            *(__half2*)(dh)     = __halves2half2(__float2half_rn(v.x), __float2half_rn(v.y));
            *(__half2*)(dh + 4) = __halves2half2(__float2half_rn(v.z), __float2half_rn(v.w));
        }
        #pragma unroll
        for (int p = 0; p < 2; ++p)
            #pragma unroll
            for (int j = 0; j < 4; ++j) acc[p][j] = 0.f;
        #pragma unroll 1
        for (int kc = 0; kc < 4; ++kc) {
            if (kc < 3) { CP_WAIT1(); } else { CP_WAIT0(); }
            __syncthreads();
            if (kc + 2 < 4) {
                stageA_sp(sb + OFF_A + (uint32_t)((kc + 2) % 3) * A_BUF,
                          g_W2_hi, g_W2_lo, b0, (kc + 2) * 128, tid);
                stageB_hi(sb + OFF_B + (uint32_t)((kc + 2) % 3) * B_BUF,
                          g_Tt_hi, h0, (kc + 2) * 128, tid);
                CP_COMMIT();
            }
            if (kc == 0) {
                chunk_Bsplit<1>(sb + OFF_X, 80u,
                                sb + OFF_BX, BX_PART, 80u, mw, nw, lane, kseg, acc);
            }
            chunk_Asplit<4>(sb + OFF_A + (uint32_t)(kc % 3) * A_BUF, A_PART, 272u,
                            sb + OFF_B + (uint32_t)(kc % 3) * B_BUF, 272u,
                            mw, nw, lane, kseg * 4, acc);
        }
        kseg_reduce(sb, kseg, mw, nw, lane, acc);

        // integrate (kseg0); hy -> O smem tile
        if (kseg == 0) {
            #pragma unroll
            for (int p = 0; p < 2; ++p) {
                #pragma unroll
                for (int j = 0; j < 4; ++j) {
                    int hc = nw * 16 + p * 8 + 2 * (lane & 3) + (j & 1);
                    int bl = mw * 16 + (lane >> 2) + ((j >> 1) * 8);
                    float hy = hyr[p][j], hz = hzr[p][j];
                    hz += DTF * (acc[p][j] - scp[32 + hc] * hy - scp[64 + hc] * hz);
                    hy += DTF * hz;
                    hzr[p][j] = hz; hyr[p][j] = hy;
                    *(float*)(smem + OFF_O + bl * 144 + hc * 4) = hy;
                }
            }
        }
        __syncthreads();
        // pre-stage static W1 chunk0 (split) for next step
        if (t + 1 < Lq) {
            stageB_sp(sb + OFF_B, g_W1_hi, g_W1_lo, h0, 0, tid);
            CP_COMMIT();
        }
        {
            int r = tid >> 3, q = tid & 7;         // 64 rows x 8 float4
            float4 v = *(const float4*)(smem + OFF_O + r * 144 + q * 16);
            *(float4*)(out + (size_t)(b0 + r) * (Lq * Hq) + (size_t)t * Hq
                           + h0 + q * 4) = v;
            size_t o = (size_t)(b0 + r) * 512 + h0 + q * 4;
            *(__half2*)(g_hy_hi + o)     = __halves2half2(__float2half_rn(v.x),
                                                          __float2half_rn(v.y));
            *(__half2*)(g_hy_hi + o + 2) = __halves2half2(__float2half_rn(v.z),
                                                          __float2half_rn(v.w));
        }
        grid_barrier(gen); gen++;
    }

    // final hy (second output)
    if (write_final && kseg == 0) {
        #pragma unroll
        for (int p = 0; p < 2; ++p) {
            #pragma unroll
            for (int j = 0; j < 4; ++j) {
                int hc = nw * 16 + p * 8 + 2 * (lane & 3) + (j & 1);
                int bl = mw * 16 + (lane >> 2) + ((j >> 1) * 8);
                out[(size_t)Bq * Lq * Hq + (size_t)(b0 + bl) * Hq + h0 + hc] = hyr[p][j];
            }
        }
    }
}

extern "C" void kernel_launch(void* const* d_in, const int* in_sizes, int n_in,
                              void* d_out, int out_size) {
    const float* x    = (const float*)d_in[0];
    const float* x2h  = (const float*)d_in[1];
    const float* h2h  = (const float*)d_in[2];
    const float* h2hT = (const float*)d_in[3];
    const float* bias = (const float*)d_in[4];
    const float* gam  = (const float*)d_in[5];
    const float* eps  = (const float*)d_in[6];
    (void)in_sizes; (void)n_in;

    cudaFuncSetAttribute(coesn_mma, cudaFuncAttributeMaxDynamicSharedMemorySize, SMEM_TOT);
    const int write_final = (out_size >= Bq * Lq * Hq + Bq * Hq) ? 1 : 0;
    coesn_mma<<<NCTA, NTHR, SMEM_TOT>>>(x, x2h, h2h, h2hT, bias, gam, eps,
                                        (float*)d_out, write_final);
}

// round 13
// speedup vs baseline: 2.1520x; 1.0472x over previous
#include <cuda_runtime.h>
#include <cuda_fp16.h>
#include <cstdint>

#define Bq 512
#define Hq 512
#define Lq 512
#define Iq 32
#define DTF 0.042f
#define NCTA 128
#define NTHR 512

// ---- SMEM layout (bytes) ----
#define OFF_A   0
#define OFF_B   104448
#define OFF_X   156672
#define OFF_BX  166912
#define OFF_T   172032
#define OFF_O   181248
#define OFF_SC  190464
#define OFF_R   190848
#define SMEM_TOT 199040

#define A_PART  17408u
#define A_BUF   34816u
#define B_PART  8704u
#define B_BUF   17408u
#define BX_PART 2560u

// ---- persistent device state (hy / Tt double-buffered by step parity) ----
__device__ __align__(256) __half g_hy_hi[2][Bq*Hq];                // dyn: hi only
__device__ __align__(256) __half g_Tt_hi[2][Hq*Bq];                // T^T [h][b]: hi only
__device__ __align__(256) __half g_W1_hi[Hq*Hq], g_W1_lo[Hq*Hq];   // h2h^T: [h][k] split
__device__ __align__(256) __half g_W2_hi[Hq*Hq], g_W2_lo[Hq*Hq];   // -h2hT: [b][j] split
__device__ unsigned g_bar_count = 0u;
__device__ volatile unsigned g_bar_gen = 0u;
// subgroup barriers (padded to separate L2 lines)
__device__ unsigned g_ccnt[16 * 32];
__device__ volatile unsigned g_cgen[16 * 32];
__device__ unsigned g_rcnt[8 * 32];
__device__ volatile unsigned g_rgen[8 * 32];

__device__ __forceinline__ uint32_t smem_u32(const void* p) {
    uint32_t a;
    asm("{ .reg .u64 t; cvta.to.shared.u64 t, %1; cvt.u32.u64 %0, t; }" : "=r"(a) : "l"(p));
    return a;
}
#define CP_ASYNC16(dst, src) \
    asm volatile("cp.async.cg.shared.global [%0], [%1], 16;" :: "r"(dst), "l"(src) : "memory")
#define CP_COMMIT() asm volatile("cp.async.commit_group;" ::: "memory")
#define CP_WAIT0()  asm volatile("cp.async.wait_group 0;" ::: "memory")
#define CP_WAIT1()  asm volatile("cp.async.wait_group 1;" ::: "memory")
#define LDSM4(r0,r1,r2,r3, addr) \
    asm volatile("ldmatrix.sync.aligned.m8n8.x4.shared.b16 {%0,%1,%2,%3}, [%4];" \
        : "=r"(r0), "=r"(r1), "=r"(r2), "=r"(r3) : "r"(addr))

__device__ __forceinline__ void mma16816(float* c, uint32_t a0, uint32_t a1, uint32_t a2,
                                         uint32_t a3, uint32_t b0, uint32_t b1) {
    asm volatile(
        "mma.sync.aligned.m16n8k16.row.col.f32.f16.f16.f32 "
        "{%0,%1,%2,%3}, {%4,%5,%6,%7}, {%8,%9}, {%0,%1,%2,%3};"
        : "+f"(c[0]), "+f"(c[1]), "+f"(c[2]), "+f"(c[3])
        : "r"(a0), "r"(a1), "r"(a2), "r"(a3), "r"(b0), "r"(b1));
}

// ---- staging (BK=128, padded rows of 272B; NTHR=512) ----
__device__ __forceinline__ void stageA_hi(uint32_t dst0, const __half* __restrict__ ghi,
                                          int row0, int k0, int tid) {
    #pragma unroll
    for (int e = 0; e < 2; ++e) {
        int idx = tid + e * NTHR;
        int rem = idx & 1023, r = rem >> 4, seg = rem & 15;
        CP_ASYNC16(dst0 + (uint32_t)(r * 272 + seg * 16),
                   ghi + (size_t)(row0 + r) * 512 + k0 + seg * 8);
    }
}
__device__ __forceinline__ void stageA_sp(uint32_t dst0, const __half* __restrict__ ghi,
                                          const __half* __restrict__ glo,
                                          int row0, int k0, int tid) {
    #pragma unroll
    for (int e = 0; e < 4; ++e) {
        int idx = tid + e * NTHR;
        const __half* g = (e < 2) ? ghi : glo;
        uint32_t po = (e < 2) ? 0u : A_PART;
        int rem = idx & 1023, r = rem >> 4, seg = rem & 15;
        CP_ASYNC16(dst0 + po + (uint32_t)(r * 272 + seg * 16),
                   g + (size_t)(row0 + r) * 512 + k0 + seg * 8);
    }
}
__device__ __forceinline__ void stageB_hi(uint32_t dst0, const __half* __restrict__ ghi,
                                          int row0, int k0, int tid) {
    int r = tid >> 4, seg = tid & 15;
    CP_ASYNC16(dst0 + (uint32_t)(r * 272 + seg * 16),
               ghi + (size_t)(row0 + r) * 512 + k0 + seg * 8);
}
__device__ __forceinline__ void stageB_sp(uint32_t dst0, const __half* __restrict__ ghi,
                                          const __half* __restrict__ glo,
                                          int row0, int k0, int tid) {
    #pragma unroll
    for (int e = 0; e < 2; ++e) {
        int idx = tid + e * NTHR;
        const __half* g = (e < 1) ? ghi : glo;
        uint32_t po = (e < 1) ? 0u : B_PART;
        int rem = idx & 511, r = rem >> 4, seg = rem & 15;
        CP_ASYNC16(dst0 + po + (uint32_t)(r * 272 + seg * 16),
                   g + (size_t)(row0 + r) * 512 + k0 + seg * 8);
    }
}

// chunk with B split (A hi-only)
template<int NKSH>
__device__ __forceinline__ void chunk_Bsplit(
    uint32_t aBase, uint32_t aStr,
    uint32_t bBase, uint32_t bPart, uint32_t bStr,
    int mw, int nw, int lane, int ks0, float acc[2][4])
{
    const int m = lane >> 3, rr = lane & 7;
    const uint32_t aAddr = aBase + (uint32_t)(mw * 16 + (m & 1) * 8 + rr) * aStr
                         + (uint32_t)((m >> 1) * 16) + (uint32_t)(ks0 * 32);
    const uint32_t bAddr = bBase + (uint32_t)(nw * 16 + (m >> 1) * 8 + rr) * bStr
                         + (uint32_t)((m & 1) * 16) + (uint32_t)(ks0 * 32);
    #pragma unroll
    for (int ks = 0; ks < NKSH; ++ks) {
        uint32_t ah0, ah1, ah2, ah3;
        LDSM4(ah0, ah1, ah2, ah3, aAddr + ks * 32);
        uint32_t bh0, bh1, bh2, bh3, bl0, bl1, bl2, bl3;
        LDSM4(bh0, bh1, bh2, bh3, bAddr + ks * 32);
        LDSM4(bl0, bl1, bl2, bl3, bAddr + bPart + ks * 32);
        mma16816(acc[0], ah0, ah1, ah2, ah3, bh0, bh1);
        mma16816(acc[0], ah0, ah1, ah2, ah3, bl0, bl1);
        mma16816(acc[1], ah0, ah1, ah2, ah3, bh2, bh3);
        mma16816(acc[1], ah0, ah1, ah2, ah3, bl2, bl3);
    }
}
// chunk with A split (B hi-only)
template<int NKSH>
__device__ __forceinline__ void chunk_Asplit(
    uint32_t aBase, uint32_t aPart, uint32_t aStr,
    uint32_t bBase, uint32_t bStr,
    int mw, int nw, int lane, int ks0, float acc[2][4])
{
    const int m = lane >> 3, rr = lane & 7;
    const uint32_t aAddr = aBase + (uint32_t)(mw * 16 + (m & 1) * 8 + rr) * aStr
                         + (uint32_t)((m >> 1) * 16) + (uint32_t)(ks0 * 32);
    const uint32_t bAddr = bBase + (uint32_t)(nw * 16 + (m >> 1) * 8 + rr) * bStr
                         + (uint32_t)((m & 1) * 16) + (uint32_t)(ks0 * 32);
    #pragma unroll
    for (int ks = 0; ks < NKSH; ++ks) {
        uint32_t ah0, ah1, ah2, ah3, al0, al1, al2, al3;
        LDSM4(ah0, ah1, ah2, ah3, aAddr + ks * 32);
        LDSM4(al0, al1, al2, al3, aAddr + aPart + ks * 32);
        uint32_t bh0, bh1, bh2, bh3;
        LDSM4(bh0, bh1, bh2, bh3, bAddr + ks * 32);
        mma16816(acc[0], ah0, ah1, ah2, ah3, bh0, bh1);
        mma16816(acc[0], al0, al1, al2, al3, bh0, bh1);
        mma16816(acc[1], ah0, ah1, ah2, ah3, bh2, bh3);
        mma16816(acc[1], al0, al1, al2, al3, bh2, bh3);
    }
}

__device__ __forceinline__ void grid_barrier(unsigned gen) {
    __syncthreads();
    if (threadIdx.x == 0) {
        __threadfence();
        if (atomicAdd(&g_bar_count, 1u) == (unsigned)(NCTA - 1)) {
            g_bar_count = 0u;
            __threadfence();
            g_bar_gen = gen + 1u;
        } else {
            while (g_bar_gen == gen) { }
            __threadfence();
        }
    }
    __syncthreads();
}

// subgroup barrier over n CTAs
__device__ __forceinline__ void group_barrier(unsigned* cnt, volatile unsigned* gen,
                                              unsigned n, unsigned g) {
    __syncthreads();
    if (threadIdx.x == 0) {
        __threadfence();
        if (atomicAdd(cnt, 1u) == n - 1u) {
            *cnt = 0u;
            __threadfence();
            *gen = g + 1u;
        } else {
            while (*gen == g) { }
            __threadfence();
        }
    }
    __syncthreads();
}

// kseg reduction
__device__ __forceinline__ void kseg_reduce(uint32_t sb, int kseg, int mw, int nw,
                                            int lane, float acc[2][4]) {
    const uint32_t slot = sb + OFF_R + (uint32_t)(((mw * 2 + nw) * 32 + lane) * 32);
    if (kseg == 1) {
        asm volatile("st.shared.v4.f32 [%0], {%1,%2,%3,%4};" ::
            "r"(slot), "f"(acc[0][0]), "f"(acc[0][1]), "f"(acc[0][2]), "f"(acc[0][3]) : "memory");
        asm volatile("st.shared.v4.f32 [%0], {%1,%2,%3,%4};" ::
            "r"(slot + 16), "f"(acc[1][0]), "f"(acc[1][1]), "f"(acc[1][2]), "f"(acc[1][3]) : "memory");
    }
    __syncthreads();
    if (kseg == 0) {
        float4 v0, v1;
        asm volatile("ld.shared.v4.f32 {%0,%1,%2,%3}, [%4];"
            : "=f"(v0.x), "=f"(v0.y), "=f"(v0.z), "=f"(v0.w) : "r"(slot));
        asm volatile("ld.shared.v4.f32 {%0,%1,%2,%3}, [%4];"
            : "=f"(v1.x), "=f"(v1.y), "=f"(v1.z), "=f"(v1.w) : "r"(slot + 16));
        acc[0][0] += v0.x; acc[0][1] += v0.y; acc[0][2] += v0.z; acc[0][3] += v0.w;
        acc[1][0] += v1.x; acc[1][1] += v1.y; acc[1][2] += v1.z; acc[1][3] += v1.w;
    }
}

__global__ void __launch_bounds__(NTHR, 1) coesn_mma(
    const float* __restrict__ x,    const float* __restrict__ x2h,
    const float* __restrict__ h2h,  const float* __restrict__ h2hT,
    const float* __restrict__ bias, const float* __restrict__ gamma,
    const float* __restrict__ eps,  float* __restrict__ out, int write_final)
{
    extern __shared__ __align__(16) char smem[];
    const uint32_t sb = smem_u32(smem);
    const int tid = threadIdx.x;
    const int w = tid >> 5, lane = tid & 31;
    const int mw = w & 3, nw = (w >> 2) & 1, kseg = w >> 3;
    const int bidx = blockIdx.x;
    const int bt = bidx >> 4, ht = bidx & 15;
    const int b0 = bt * 64, h0 = ht * 32;

    unsigned gen = g_bar_gen;
    unsigned genc = g_cgen[ht * 32];
    unsigned genr = g_rgen[bt * 32];

    // ---- cooperative init ----
    const int gtid = bidx * NTHR + tid;
    #pragma unroll 1
    for (int e = 0; e < 4; ++e) {
        int idx = gtid + e * (NCTA * NTHR);
        int r = idx >> 9, c = idx & 511;
        float v1 = h2h[(size_t)c * Hq + r];
        __half h1 = __float2half_rn(v1);
        g_W1_hi[idx] = h1;
        g_W1_lo[idx] = __float2half_rn(v1 - __half2float(h1));
        float v2 = -h2hT[idx];
        __half h2v = __float2half_rn(v2);
        g_W2_hi[idx] = h2v;
        g_W2_lo[idx] = __float2half_rn(v2 - __half2float(h2v));
        g_hy_hi[0][idx] = __float2half_rn(0.f);
    }
    #pragma unroll
    for (int e = 0; e < 4; ++e) {
        int idx = tid + e * NTHR;
        int part = (idx >= 1024);
        int rem = idx & 1023, r = rem >> 5, ii = rem & 31;
        float v = x2h[(size_t)ii * Hq + h0 + r];
        __half hv = __float2half_rn(v);
        __half val = part ? __float2half_rn(v - __half2float(hv)) : hv;
        *(__half*)(smem + OFF_BX + part * BX_PART + r * 80 + ii * 2) = val;
    }
    if (tid < 32) {
        ((float*)(smem + OFF_SC))[tid]      = bias[h0 + tid];
        ((float*)(smem + OFF_SC))[32 + tid] = gamma[h0 + tid];
        ((float*)(smem + OFF_SC))[64 + tid] = eps[h0 + tid];
    }
    const float* scp = (const float*)(smem + OFF_SC);
    grid_barrier(gen); gen++;

    // pre-stage static W1 chunk0 (split) for the first phase-1
    stageB_sp(sb + OFF_B, g_W1_hi, g_W1_lo, h0, 0, tid);
    CP_COMMIT();

    float hyr[2][4], hzr[2][4];
    #pragma unroll
    for (int p = 0; p < 2; ++p)
        #pragma unroll
        for (int j = 0; j < 4; ++j) { hyr[p][j] = 0.f; hzr[p][j] = 0.f; }

    #pragma unroll 1
    for (int t = 0; t < Lq; ++t) {
        const int pt = t & 1;
        const __half* hyH = g_hy_hi[pt];
        const __half* TtH = g_Tt_hi[pt];

        // ===== Phase 1: D1 = hy @ h2h (A=hy hi, B=W1 split) =====
        float acc[2][4];
        #pragma unroll
        for (int p = 0; p < 2; ++p)
            #pragma unroll
            for (int j = 0; j < 4; ++j) acc[p][j] = 0.f;

        stageA_hi(sb + OFF_A, hyH, b0, 0, tid);
        CP_COMMIT();
        stageA_hi(sb + OFF_A + A_BUF, hyH, b0, 128, tid);
        stageB_sp(sb + OFF_B + B_BUF, g_W1_hi, g_W1_lo, h0, 128, tid);
        CP_COMMIT();
        #pragma unroll 1
        for (int kc = 0; kc < 4; ++kc) {
            if (kc < 3) { CP_WAIT1(); } else { CP_WAIT0(); }
            __syncthreads();
            if (kc + 2 < 4) {
                stageA_hi(sb + OFF_A + (uint32_t)((kc + 2) % 3) * A_BUF,
                          hyH, b0, (kc + 2) * 128, tid);
                stageB_sp(sb + OFF_B + (uint32_t)((kc + 2) % 3) * B_BUF,
                          g_W1_hi, g_W1_lo, h0, (kc + 2) * 128, tid);
                CP_COMMIT();
            }
            chunk_Bsplit<4>(sb + OFF_A + (uint32_t)(kc % 3) * A_BUF, 272u,
                            sb + OFF_B + (uint32_t)(kc % 3) * B_BUF, B_PART, 272u,
                            mw, nw, lane, kseg * 4, acc);
        }
        kseg_reduce(sb, kseg, mw, nw, lane, acc);

        // tanh -> T smem (hi only; kseg0 warps)
        if (kseg == 0) {
            #pragma unroll
            for (int p = 0; p < 2; ++p) {
                #pragma unroll
                for (int j = 0; j < 4; ++j) {
                    int hc = nw * 16 + p * 8 + 2 * (lane & 3) + (j & 1);
                    int bl = mw * 16 + (lane >> 2) + ((j >> 1) * 8);
                    float v = acc[p][j] + scp[hc];
                    float e2 = __expf(2.f * v);
                    float tv = 1.f - 2.f / (e2 + 1.f);
                    *(__half*)(smem + OFF_T + hc * 144 + bl * 2) = __float2half_rn(tv);
                }
            }
        }
        __syncthreads();
        // T -> global (parity buffer); pre-stage static W2 chunk0 (split A)
        stageA_sp(sb + OFF_A, g_W2_hi, g_W2_lo, b0, 0, tid);
        CP_COMMIT();
        if (tid < 256) {
            int r = tid >> 3, q = tid & 7;
            uint4 val = *(const uint4*)(smem + OFF_T + r * 144 + q * 16);
            *(uint4*)(g_Tt_hi[pt] + (size_t)(h0 + r) * 512 + b0 + q * 8) = val;
        }
        group_barrier(&g_ccnt[ht * 32], &g_cgen[ht * 32], 8u, genc); genc++;

        // ===== Phase 2: D2 = x_t @ x2h - h2hT @ T (A=W2 split, B=Tt hi) =====
        stageB_hi(sb + OFF_B, TtH, h0, 0, tid);
        CP_COMMIT();
        stageA_sp(sb + OFF_A + A_BUF, g_W2_hi, g_W2_lo, b0, 128, tid);
        stageB_hi(sb + OFF_B + B_BUF, TtH, h0, 128, tid);
        CP_COMMIT();
        // x_t (hi only) -> X SMEM
        {
            int r = tid >> 3, q = tid & 7;
            float4 v = *(const float4*)(x + (size_t)(b0 + r) * (Lq * Iq)
                                          + (size_t)t * Iq + q * 4);
            char* dh = smem + OFF_X + r * 80 + q * 8;
            *(__half2*)(dh)     = __halves2half2(__float2half_rn(v.x), __float2half_rn(v.y));
            *(__half2*)(dh + 4) = __halves2half2(__float2half_rn(v.z), __float2half_rn(v.w));
        }
        #pragma unroll
        for (int p = 0; p < 2; ++p)
            #pragma unroll
            for (int j = 0; j < 4; ++j) acc[p][j] = 0.f;
        #pragma unroll 1
        for (int kc = 0; kc < 4; ++kc) {
            if (kc < 3) { CP_WAIT1(); } else { CP_WAIT0(); }
            __syncthreads();
            if (kc + 2 < 4) {
                stageA_sp(sb + OFF_A + (uint32_t)((kc + 2) % 3) * A_BUF,
                          g_W2_hi, g_W2_lo, b0, (kc + 2) * 128, tid);
                stageB_hi(sb + OFF_B + (uint32_t)((kc + 2) % 3) * B_BUF,
                          TtH, h0, (kc + 2) * 128, tid);
                CP_COMMIT();
            }
            if (kc == 0) {
                chunk_Bsplit<1>(sb + OFF_X, 80u,
                                sb + OFF_BX, BX_PART, 80u, mw, nw, lane, kseg, acc);
            }
            chunk_Asplit<4>(sb + OFF_A + (uint32_t)(kc % 3) * A_BUF, A_PART, 272u,
                            sb + OFF_B + (uint32_t)(kc % 3) * B_BUF, 272u,
                            mw, nw, lane, kseg * 4, acc);
        }
        kseg_reduce(sb, kseg, mw, nw, lane, acc);

        // integrate (kseg0); hy -> O smem tile
        if (kseg == 0) {
            #pragma unroll
            for (int p = 0; p < 2; ++p) {
                #pragma unroll
                for (int j = 0; j < 4; ++j) {
                    int hc = nw * 16 + p * 8 + 2 * (lane & 3) + (j & 1);
                    int bl = mw * 16 + (lane >> 2) + ((j >> 1) * 8);
                    float hy = hyr[p][j], hz = hzr[p][j];
                    hz += DTF * (acc[p][j] - scp[32 + hc] * hy - scp[64 + hc] * hz);
                    hy += DTF * hz;
                    hzr[p][j] = hz; hyr[p][j] = hy;
                    *(float*)(smem + OFF_O + bl * 144 + hc * 4) = hy;
                }
            }
        }
        __syncthreads();
        // pre-stage static W1 chunk0 (split) for next step
        if (t + 1 < Lq) {
            stageB_sp(sb + OFF_B, g_W1_hi, g_W1_lo, h0, 0, tid);
            CP_COMMIT();
        }
        {
            int r = tid >> 3, q = tid & 7;
            float4 v = *(const float4*)(smem + OFF_O + r * 144 + q * 16);
            *(float4*)(out + (size_t)(b0 + r) * (Lq * Hq) + (size_t)t * Hq
                           + h0 + q * 4) = v;
            size_t o = (size_t)(b0 + r) * 512 + h0 + q * 4;
            __half* hyD = g_hy_hi[(t + 1) & 1];
            *(__half2*)(hyD + o)     = __halves2half2(__float2half_rn(v.x),
                                                      __float2half_rn(v.y));
            *(__half2*)(hyD + o + 2) = __halves2half2(__float2half_rn(v.z),
                                                      __float2half_rn(v.w));
        }
        group_barrier(&g_rcnt[bt * 32], &g_rgen[bt * 32], 16u, genr); genr++;
    }

    // final hy (second output)
    if (write_final && kseg == 0) {
        #pragma unroll
        for (int p = 0; p < 2; ++p) {
            #pragma unroll
            for (int j = 0; j < 4; ++j) {
                int hc = nw * 16 + p * 8 + 2 * (lane & 3) + (j & 1);
                int bl = mw * 16 + (lane >> 2) + ((j >> 1) * 8);
                out[(size_t)Bq * Lq * Hq + (size_t)(b0 + bl) * Hq + h0 + hc] = hyr[p][j];
            }
        }
    }
}

extern "C" void kernel_launch(void* const* d_in, const int* in_sizes, int n_in,
                              void* d_out, int out_size) {
    const float* x    = (const float*)d_in[0];
    const float* x2h  = (const float*)d_in[1];
    const float* h2h  = (const float*)d_in[2];
    const float* h2hT = (const float*)d_in[3];
    const float* bias = (const float*)d_in[4];
    const float* gam  = (const float*)d_in[5];
    const float* eps  = (const float*)d_in[6];
    (void)in_sizes; (void)n_in;

    cudaFuncSetAttribute(coesn_mma, cudaFuncAttributeMaxDynamicSharedMemorySize, SMEM_TOT);
    const int write_final = (out_size >= Bq * Lq * Hq + Bq * Hq) ? 1 : 0;
    coesn_mma<<<NCTA, NTHR, SMEM_TOT>>>(x, x2h, h2h, h2hT, bias, gam, eps,
                                        (float*)d_out, write_final);
}

// round 15
// speedup vs baseline: 2.2472x; 1.0443x over previous
#include <cuda_runtime.h>
#include <cuda_fp16.h>
#include <cstdint>

#define Bq 512
#define Hq 512
#define Lq 512
#define Iq 32
#define DTF 0.042f
#define NCTA 128
#define NTHR 512

// ---- SMEM layout (bytes) ----
#define OFF_A    0                    // 3 x 34816 (hi part at +0, lo part at +17408)
#define OFF_B    104448               // 3 x 8704 (phase2 B = Tt hi)
#define OFF_W1P  130560               // persistent W1 split: 2 part x 32 rows x 1040B
#define OFF_X    197120               // x hi: 64 x 80B
#define OFF_BX   202240               // x2hT split: 2 x 2560
#define OFF_T    207360               // T hi: 32 x 144B
#define OFF_O    211968               // 64 x 144B
#define OFF_SC   221184               // 3 x 32 floats
#define OFF_R    221568               // kseg reduce: 8192
#define SMEM_TOT 229760

#define A_PART  17408u
#define A_BUF   34816u
#define B_BUF   8704u
#define BX_PART 2560u
#define W1_STR  1040u
#define W1_PART 33280u

// ---- persistent device state (hy / Tt double-buffered by step parity) ----
__device__ __align__(256) __half g_hy_hi[2][Bq*Hq];                // dyn: hi only
__device__ __align__(256) __half g_Tt_hi[2][Hq*Bq];                // T^T [h][b]: hi only
__device__ __align__(256) __half g_W1_hi[Hq*Hq], g_W1_lo[Hq*Hq];   // h2h^T: [h][k] split
__device__ __align__(256) __half g_W2_hi[Hq*Hq], g_W2_lo[Hq*Hq];   // -h2hT: [b][j] split
__device__ unsigned g_bar_count = 0u;
__device__ volatile unsigned g_bar_gen = 0u;
__device__ unsigned g_ccnt[16 * 32];
__device__ volatile unsigned g_cgen[16 * 32];
__device__ unsigned g_rcnt[8 * 32];
__device__ volatile unsigned g_rgen[8 * 32];

__device__ __forceinline__ uint32_t smem_u32(const void* p) {
    uint32_t a;
    asm("{ .reg .u64 t; cvta.to.shared.u64 t, %1; cvt.u32.u64 %0, t; }" : "=r"(a) : "l"(p));
    return a;
}
#define CP_ASYNC16(dst, src) \
    asm volatile("cp.async.cg.shared.global [%0], [%1], 16;" :: "r"(dst), "l"(src) : "memory")
#define CP_COMMIT() asm volatile("cp.async.commit_group;" ::: "memory")
#define CP_WAIT0()  asm volatile("cp.async.wait_group 0;" ::: "memory")
#define CP_WAIT1()  asm volatile("cp.async.wait_group 1;" ::: "memory")
#define LDSM4(r0,r1,r2,r3, addr) \
    asm volatile("ldmatrix.sync.aligned.m8n8.x4.shared.b16 {%0,%1,%2,%3}, [%4];" \
        : "=r"(r0), "=r"(r1), "=r"(r2), "=r"(r3) : "r"(addr))

__device__ __forceinline__ void mma16816(float* c, uint32_t a0, uint32_t a1, uint32_t a2,
                                         uint32_t a3, uint32_t b0, uint32_t b1) {
    asm volatile(
        "mma.sync.aligned.m16n8k16.row.col.f32.f16.f16.f32 "
        "{%0,%1,%2,%3}, {%4,%5,%6,%7}, {%8,%9}, {%0,%1,%2,%3};"
        : "+f"(c[0]), "+f"(c[1]), "+f"(c[2]), "+f"(c[3])
        : "r"(a0), "r"(a1), "r"(a2), "r"(a3), "r"(b0), "r"(b1));
}

// ---- staging ----
__device__ __forceinline__ void stageA_hi(uint32_t dst0, const __half* __restrict__ ghi,
                                          int row0, int k0, int tid) {
    #pragma unroll
    for (int e = 0; e < 2; ++e) {                 // 64 rows x 16 segs
        int idx = tid + e * NTHR;
        int rem = idx & 1023, r = rem >> 4, seg = rem & 15;
        CP_ASYNC16(dst0 + (uint32_t)(r * 272 + seg * 16),
                   ghi + (size_t)(row0 + r) * 512 + k0 + seg * 8);
    }
}
__device__ __forceinline__ void stageA_sp(uint32_t dst0, const __half* __restrict__ ghi,
                                          const __half* __restrict__ glo,
                                          int row0, int k0, int tid) {
    #pragma unroll
    for (int e = 0; e < 4; ++e) {                 // 2 part x 64 rows x 16 segs
        int idx = tid + e * NTHR;
        const __half* g = (e < 2) ? ghi : glo;
        uint32_t po = (e < 2) ? 0u : A_PART;
        int rem = idx & 1023, r = rem >> 4, seg = rem & 15;
        CP_ASYNC16(dst0 + po + (uint32_t)(r * 272 + seg * 16),
                   g + (size_t)(row0 + r) * 512 + k0 + seg * 8);
    }
}
__device__ __forceinline__ void stageB_hi(uint32_t dst0, const __half* __restrict__ ghi,
                                          int row0, int k0, int tid) {
    int r = tid >> 4, seg = tid & 15;             // 32 rows x 16 segs
    CP_ASYNC16(dst0 + (uint32_t)(r * 272 + seg * 16),
               ghi + (size_t)(row0 + r) * 512 + k0 + seg * 8);
}

// chunk with B split (A hi-only)
template<int NKSH>
__device__ __forceinline__ void chunk_Bsplit(
    uint32_t aBase, uint32_t aStr,
    uint32_t bBase, uint32_t bPart, uint32_t bStr,
    int mw, int nw, int lane, int ks0, float acc[2][4])
{
    const int m = lane >> 3, rr = lane & 7;
    const uint32_t aAddr = aBase + (uint32_t)(mw * 16 + (m & 1) * 8 + rr) * aStr
                         + (uint32_t)((m >> 1) * 16) + (uint32_t)(ks0 * 32);
    const uint32_t bAddr = bBase + (uint32_t)(nw * 16 + (m >> 1) * 8 + rr) * bStr
                         + (uint32_t)((m & 1) * 16) + (uint32_t)(ks0 * 32);
    #pragma unroll
    for (int ks = 0; ks < NKSH; ++ks) {
        uint32_t ah0, ah1, ah2, ah3;
        LDSM4(ah0, ah1, ah2, ah3, aAddr + ks * 32);
        uint32_t bh0, bh1, bh2, bh3, bl0, bl1, bl2, bl3;
        LDSM4(bh0, bh1, bh2, bh3, bAddr + ks * 32);
        LDSM4(bl0, bl1, bl2, bl3, bAddr + bPart + ks * 32);
        mma16816(acc[0], ah0, ah1, ah2, ah3, bh0, bh1);
        mma16816(acc[0], ah0, ah1, ah2, ah3, bl0, bl1);
        mma16816(acc[1], ah0, ah1, ah2, ah3, bh2, bh3);
        mma16816(acc[1], ah0, ah1, ah2, ah3, bl2, bl3);
    }
}
// chunk with A split (B hi-only)
template<int NKSH>
__device__ __forceinline__ void chunk_Asplit(
    uint32_t aBase, uint32_t aPart, uint32_t aStr,
    uint32_t bBase, uint32_t bStr,
    int mw, int nw, int lane, int ks0, float acc[2][4])
{
    const int m = lane >> 3, rr = lane & 7;
    const uint32_t aAddr = aBase + (uint32_t)(mw * 16 + (m & 1) * 8 + rr) * aStr
                         + (uint32_t)((m >> 1) * 16) + (uint32_t)(ks0 * 32);
    const uint32_t bAddr = bBase + (uint32_t)(nw * 16 + (m >> 1) * 8 + rr) * bStr
                         + (uint32_t)((m & 1) * 16) + (uint32_t)(ks0 * 32);
    #pragma unroll
    for (int ks = 0; ks < NKSH; ++ks) {
        uint32_t ah0, ah1, ah2, ah3, al0, al1, al2, al3;
        LDSM4(ah0, ah1, ah2, ah3, aAddr + ks * 32);
        LDSM4(al0, al1, al2, al3, aAddr + aPart + ks * 32);
        uint32_t bh0, bh1, bh2, bh3;
        LDSM4(bh0, bh1, bh2, bh3, bAddr + ks * 32);
        mma16816(acc[0], ah0, ah1, ah2, ah3, bh0, bh1);
        mma16816(acc[0], al0, al1, al2, al3, bh0, bh1);
        mma16816(acc[1], ah0, ah1, ah2, ah3, bh2, bh3);
        mma16816(acc[1], al0, al1, al2, al3, bh2, bh3);
    }
}

__device__ __forceinline__ void grid_barrier(unsigned gen) {
    __syncthreads();
    if (threadIdx.x == 0) {
        __threadfence();
        if (atomicAdd(&g_bar_count, 1u) == (unsigned)(NCTA - 1)) {
            g_bar_count = 0u;
            __threadfence();
            g_bar_gen = gen + 1u;
        } else {
            while (g_bar_gen == gen) { }
            __threadfence();
        }
    }
    __syncthreads();
}
__device__ __forceinline__ void group_barrier(unsigned* cnt, volatile unsigned* gen,
                                              unsigned n, unsigned g) {
    __syncthreads();
    if (threadIdx.x == 0) {
        __threadfence();
        if (atomicAdd(cnt, 1u) == n - 1u) {
            *cnt = 0u;
            __threadfence();
            *gen = g + 1u;
        } else {
            while (*gen == g) { }
            __threadfence();
        }
    }
    __syncthreads();
}

__device__ __forceinline__ void kseg_reduce(uint32_t sb, int kseg, int mw, int nw,
                                            int lane, float acc[2][4]) {
    const uint32_t slot = sb + OFF_R + (uint32_t)(((mw * 2 + nw) * 32 + lane) * 32);
    if (kseg == 1) {
        asm volatile("st.shared.v4.f32 [%0], {%1,%2,%3,%4};" ::
            "r"(slot), "f"(acc[0][0]), "f"(acc[0][1]), "f"(acc[0][2]), "f"(acc[0][3]) : "memory");
        asm volatile("st.shared.v4.f32 [%0], {%1,%2,%3,%4};" ::
            "r"(slot + 16), "f"(acc[1][0]), "f"(acc[1][1]), "f"(acc[1][2]), "f"(acc[1][3]) : "memory");
    }
    __syncthreads();
    if (kseg == 0) {
        float4 v0, v1;
        asm volatile("ld.shared.v4.f32 {%0,%1,%2,%3}, [%4];"
            : "=f"(v0.x), "=f"(v0.y), "=f"(v0.z), "=f"(v0.w) : "r"(slot));
        asm volatile("ld.shared.v4.f32 {%0,%1,%2,%3}, [%4];"
            : "=f"(v1.x), "=f"(v1.y), "=f"(v1.z), "=f"(v1.w) : "r"(slot + 16));
        acc[0][0] += v0.x; acc[0][1] += v0.y; acc[0][2] += v0.z; acc[0][3] += v0.w;
        acc[1][0] += v1.x; acc[1][1] += v1.y; acc[1][2] += v1.z; acc[1][3] += v1.w;
    }
}

__global__ void __launch_bounds__(NTHR, 1) coesn_mma(
    const float* __restrict__ x,    const float* __restrict__ x2h,
    const float* __restrict__ h2h,  const float* __restrict__ h2hT,
    const float* __restrict__ bias, const float* __restrict__ gamma,
    const float* __restrict__ eps,  float* __restrict__ out, int write_final)
{
    extern __shared__ __align__(16) char smem[];
    const uint32_t sb = smem_u32(smem);
    const int tid = threadIdx.x;
    const int w = tid >> 5, lane = tid & 31;
    const int mw = w & 3, nw = (w >> 2) & 1, kseg = w >> 3;
    const int bidx = blockIdx.x;
    const int bt = bidx >> 4, ht = bidx & 15;
    const int b0 = bt * 64, h0 = ht * 32;

    unsigned gen = g_bar_gen;
    unsigned genc = g_cgen[ht * 32];
    unsigned genr = g_rgen[bt * 32];

    // ---- cooperative init ----
    const int gtid = bidx * NTHR + tid;
    #pragma unroll 1
    for (int e = 0; e < 4; ++e) {
        int idx = gtid + e * (NCTA * NTHR);
        int r = idx >> 9, c = idx & 511;
        float v1 = h2h[(size_t)c * Hq + r];
        __half h1 = __float2half_rn(v1);
        g_W1_hi[idx] = h1;
        g_W1_lo[idx] = __float2half_rn(v1 - __half2float(h1));
        float v2 = -h2hT[idx];
        __half h2v = __float2half_rn(v2);
        g_W2_hi[idx] = h2v;
        g_W2_lo[idx] = __float2half_rn(v2 - __half2float(h2v));
        g_hy_hi[0][idx] = __float2half_rn(0.f);
    }
    #pragma unroll
    for (int e = 0; e < 4; ++e) {
        int idx = tid + e * NTHR;
        int part = (idx >= 1024);
        int rem = idx & 1023, r = rem >> 5, ii = rem & 31;
        float v = x2h[(size_t)ii * Hq + h0 + r];
        __half hv = __float2half_rn(v);
        __half val = part ? __float2half_rn(v - __half2float(hv)) : hv;
        *(__half*)(smem + OFF_BX + part * BX_PART + r * 80 + ii * 2) = val;
    }
    if (tid < 32) {
        ((float*)(smem + OFF_SC))[tid]      = bias[h0 + tid];
        ((float*)(smem + OFF_SC))[32 + tid] = gamma[h0 + tid];
        ((float*)(smem + OFF_SC))[64 + tid] = eps[h0 + tid];
    }
    const float* scp = (const float*)(smem + OFF_SC);
    grid_barrier(gen); gen++;

    // ---- stage persistent W1 slice (split): 2 part x 32 rows x 512 k ----
    #pragma unroll
    for (int e = 0; e < 8; ++e) {
        int idx = tid + e * NTHR;                  // 0..4095
        int part = idx >> 11;
        int rem = idx & 2047, r = rem >> 6, seg = rem & 63;
        const __half* g = part ? g_W1_lo : g_W1_hi;
        CP_ASYNC16(sb + OFF_W1P + (uint32_t)part * W1_PART
                      + (uint32_t)(r * 1040 + seg * 16),
                   g + (size_t)(h0 + r) * 512 + seg * 8);
    }
    CP_COMMIT(); CP_WAIT0();
    __syncthreads();

    float hyr[2][4], hzr[2][4];
    #pragma unroll
    for (int p = 0; p < 2; ++p)
        #pragma unroll
        for (int j = 0; j < 4; ++j) { hyr[p][j] = 0.f; hzr[p][j] = 0.f; }

    #pragma unroll 1
    for (int t = 0; t < Lq; ++t) {
        const int pt = t & 1;
        const __half* hyH = g_hy_hi[pt];
        const __half* TtH = g_Tt_hi[pt];

        // ===== Phase 1: D1 = hy @ h2h (A=hy hi streamed, B=W1 persistent) =====
        float acc[2][4];
        #pragma unroll
        for (int p = 0; p < 2; ++p)
            #pragma unroll
            for (int j = 0; j < 4; ++j) acc[p][j] = 0.f;

        stageA_hi(sb + OFF_A, hyH, b0, 0, tid);
        CP_COMMIT();
        stageA_hi(sb + OFF_A + A_BUF, hyH, b0, 128, tid);
        CP_COMMIT();
        #pragma unroll 1
        for (int kc = 0; kc < 4; ++kc) {
            if (kc < 3) { CP_WAIT1(); } else { CP_WAIT0(); }
            __syncthreads();
            if (kc + 2 < 4) {
                stageA_hi(sb + OFF_A + (uint32_t)((kc + 2) % 3) * A_BUF,
                          hyH, b0, (kc + 2) * 128, tid);
                CP_COMMIT();
            }
            chunk_Bsplit<4>(sb + OFF_A + (uint32_t)(kc % 3) * A_BUF, 272u,
                            sb + OFF_W1P + (uint32_t)(kc * 256), W1_PART, W1_STR,
                            mw, nw, lane, kseg * 4, acc);
        }
        kseg_reduce(sb, kseg, mw, nw, lane, acc);

        // tanh -> T smem (hi only; kseg0 warps)
        if (kseg == 0) {
            #pragma unroll
            for (int p = 0; p < 2; ++p) {
                #pragma unroll
                for (int j = 0; j < 4; ++j) {
                    int hc = nw * 16 + p * 8 + 2 * (lane & 3) + (j & 1);
                    int bl = mw * 16 + (lane >> 2) + ((j >> 1) * 8);
                    float v = acc[p][j] + scp[hc];
                    float e2 = __expf(2.f * v);
                    float tv = 1.f - 2.f / (e2 + 1.f);
                    *(__half*)(smem + OFF_T + hc * 144 + bl * 2) = __float2half_rn(tv);
                }
            }
        }
        __syncthreads();
        // T -> global (parity buffer); pre-stage static W2 chunk0 (split A)
        stageA_sp(sb + OFF_A, g_W2_hi, g_W2_lo, b0, 0, tid);
        CP_COMMIT();
        if (tid < 256) {
            int r = tid >> 3, q = tid & 7;
            uint4 val = *(const uint4*)(smem + OFF_T + r * 144 + q * 16);
            *(uint4*)(g_Tt_hi[pt] + (size_t)(h0 + r) * 512 + b0 + q * 8) = val;
        }
        group_barrier(&g_ccnt[ht * 32], &g_cgen[ht * 32], 8u, genc); genc++;

        // ===== Phase 2: D2 = x_t @ x2h - h2hT @ T (A=W2 split, B=Tt hi) =====
        stageB_hi(sb + OFF_B, TtH, h0, 0, tid);
        CP_COMMIT();
        stageA_sp(sb + OFF_A + A_BUF, g_W2_hi, g_W2_lo, b0, 128, tid);
        stageB_hi(sb + OFF_B + B_BUF, TtH, h0, 128, tid);
        CP_COMMIT();
        // x_t (hi only) -> X SMEM (visibility via kc=0 __syncthreads)
        {
            int r = tid >> 3, q = tid & 7;
            float4 v = *(const float4*)(x + (size_t)(b0 + r) * (Lq * Iq)
                                          + (size_t)t * Iq + q * 4);
            char* dh = smem + OFF_X + r * 80 + q * 8;
            *(__half2*)(dh)     = __halves2half2(__float2half_rn(v.x), __float2half_rn(v.y));
            *(__half2*)(dh + 4) = __halves2half2(__float2half_rn(v.z), __float2half_rn(v.w));
        }
        #pragma unroll
        for (int p = 0; p < 2; ++p)
            #pragma unroll
            for (int j = 0; j < 4; ++j) acc[p][j] = 0.f;
        #pragma unroll 1
        for (int kc = 0; kc < 4; ++kc) {
            if (kc < 3) { CP_WAIT1(); } else { CP_WAIT0(); }
            __syncthreads();
            if (kc + 2 < 4) {
                stageA_sp(sb + OFF_A + (uint32_t)((kc + 2) % 3) * A_BUF,
                          g_W2_hi, g_W2_lo, b0, (kc + 2) * 128, tid);
                stageB_hi(sb + OFF_B + (uint32_t)((kc + 2) % 3) * B_BUF,
                          TtH, h0, (kc + 2) * 128, tid);
                CP_COMMIT();
            }
            if (kc == 0) {
                chunk_Bsplit<1>(sb + OFF_X, 80u,
                                sb + OFF_BX, BX_PART, 80u, mw, nw, lane, kseg, acc);
            }
            chunk_Asplit<4>(sb + OFF_A + (uint32_t)(kc % 3) * A_BUF, A_PART, 272u,
                            sb + OFF_B + (uint32_t)(kc % 3) * B_BUF, 272u,
                            mw, nw, lane, kseg * 4, acc);
        }
        kseg_reduce(sb, kseg, mw, nw, lane, acc);

        // integrate (kseg0); hy -> O smem tile
        if (kseg == 0) {
            #pragma unroll
            for (int p = 0; p < 2; ++p) {
                #pragma unroll
                for (int j = 0; j < 4; ++j) {
                    int hc = nw * 16 + p * 8 + 2 * (lane & 3) + (j & 1);
                    int bl = mw * 16 + (lane >> 2) + ((j >> 1) * 8);
                    float hy = hyr[p][j], hz = hzr[p][j];
                    hz += DTF * (acc[p][j] - scp[32 + hc] * hy - scp[64 + hc] * hz);
                    hy += DTF * hz;
                    hzr[p][j] = hz; hyr[p][j] = hy;
                    *(float*)(smem + OFF_O + bl * 144 + hc * 4) = hy;
                }
            }
        }
        __syncthreads();
        {
            int r = tid >> 3, q = tid & 7;
            float4 v = *(const float4*)(smem + OFF_O + r * 144 + q * 16);
            *(float4*)(out + (size_t)(b0 + r) * (Lq * Hq) + (size_t)t * Hq
                           + h0 + q * 4) = v;
            size_t o = (size_t)(b0 + r) * 512 + h0 + q * 4;
            __half* hyD = g_hy_hi[(t + 1) & 1];
            *(__half2*)(hyD + o)     = __halves2half2(__float2half_rn(v.x),
                                                      __float2half_rn(v.y));
            *(__half2*)(hyD + o + 2) = __halves2half2(__float2half_rn(v.z),
                                                      __float2half_rn(v.w));
        }
        group_barrier(&g_rcnt[bt * 32], &g_rgen[bt * 32], 16u, genr); genr++;
    }

    // final hy (second output)
    if (write_final && kseg == 0) {
        #pragma unroll
        for (int p = 0; p < 2; ++p) {
            #pragma unroll
            for (int j = 0; j < 4; ++j) {
                int hc = nw * 16 + p * 8 + 2 * (lane & 3) + (j & 1);
                int bl = mw * 16 + (lane >> 2) + ((j >> 1) * 8);
                out[(size_t)Bq * Lq * Hq + (size_t)(b0 + bl) * Hq + h0 + hc] = hyr[p][j];
            }
        }
    }
}

extern "C" void kernel_launch(void* const* d_in, const int* in_sizes, int n_in,
                              void* d_out, int out_size) {
    const float* x    = (const float*)d_in[0];
    const float* x2h  = (const float*)d_in[1];
    const float* h2h  = (const float*)d_in[2];
    const float* h2hT = (const float*)d_in[3];
    const float* bias = (const float*)d_in[4];
    const float* gam  = (const float*)d_in[5];
    const float* eps  = (const float*)d_in[6];
    (void)in_sizes; (void)n_in;

    cudaFuncSetAttribute(coesn_mma, cudaFuncAttributeMaxDynamicSharedMemorySize, SMEM_TOT);
    const int write_final = (out_size >= Bq * Lq * Hq + Bq * Hq) ? 1 : 0;
    coesn_mma<<<NCTA, NTHR, SMEM_TOT>>>(x, x2h, h2h, h2hT, bias, gam, eps,
                                        (float*)d_out, write_final);
}

// round 16
// speedup vs baseline: 2.7449x; 1.2215x over previous
#include <cuda_runtime.h>
#include <cuda_fp16.h>
#include <cstdint>

#define Bq 512
#define Hq 512
#define Lq 512
#define Iq 32
#define DTF 0.042f
#define NCTA 128
#define NTHR 512

// ---- SMEM layout (bytes) ----
#define OFF_A    0                    // 3 x 17408: phase-1 hy_hi chunks (64 x 272)
#define OFF_B    52224                // 3 x 8704:  phase-2 Tt_hi chunks (32 x 272)
#define OFF_W1P  78336                // persistent W1 hi: 32 rows x 1040
#define OFF_W2P  111616               // persistent W2 hi: 64 rows x 1040
#define OFF_X    178176               // x hi: 64 x 80
#define OFF_BX   183296               // x2hT hi: 32 x 80
#define OFF_T    185856               // T hi: 32 x 144
#define OFF_O    190464               // 64 x 144
#define OFF_SC   199680               // 3 x 32 floats
#define OFF_R    200064               // kseg reduce: 8192
#define SMEM_TOT 208256

#define A_BUF   17408u
#define B_BUF   8704u
#define W_STR   1040u

// ---- persistent device state (hy / Tt double-buffered by step parity) ----
__device__ __align__(256) __half g_hy_hi[2][Bq*Hq];
__device__ __align__(256) __half g_Tt_hi[2][Hq*Bq];        // T^T [h][b]
__device__ __align__(256) __half g_W1_hi[Hq*Hq];           // h2h^T: [h][k]
__device__ __align__(256) __half g_W2_hi[Hq*Hq];           // -h2hT: [b][j]
__device__ unsigned g_bar_count = 0u;
__device__ volatile unsigned g_bar_gen = 0u;
__device__ unsigned g_ccnt[16 * 32];
__device__ volatile unsigned g_cgen[16 * 32];
__device__ unsigned g_rcnt[8 * 32];
__device__ volatile unsigned g_rgen[8 * 32];

__device__ __forceinline__ uint32_t smem_u32(const void* p) {
    uint32_t a;
    asm("{ .reg .u64 t; cvta.to.shared.u64 t, %1; cvt.u32.u64 %0, t; }" : "=r"(a) : "l"(p));
    return a;
}
#define CP_ASYNC16(dst, src) \
    asm volatile("cp.async.cg.shared.global [%0], [%1], 16;" :: "r"(dst), "l"(src) : "memory")
#define CP_COMMIT() asm volatile("cp.async.commit_group;" ::: "memory")
#define CP_WAIT0()  asm volatile("cp.async.wait_group 0;" ::: "memory")
#define CP_WAIT1()  asm volatile("cp.async.wait_group 1;" ::: "memory")
#define LDSM4(r0,r1,r2,r3, addr) \
    asm volatile("ldmatrix.sync.aligned.m8n8.x4.shared.b16 {%0,%1,%2,%3}, [%4];" \
        : "=r"(r0), "=r"(r1), "=r"(r2), "=r"(r3) : "r"(addr))

__device__ __forceinline__ void mma16816(float* c, uint32_t a0, uint32_t a1, uint32_t a2,
                                         uint32_t a3, uint32_t b0, uint32_t b1) {
    asm volatile(
        "mma.sync.aligned.m16n8k16.row.col.f32.f16.f16.f32 "
        "{%0,%1,%2,%3}, {%4,%5,%6,%7}, {%8,%9}, {%0,%1,%2,%3};"
        : "+f"(c[0]), "+f"(c[1]), "+f"(c[2]), "+f"(c[3])
        : "r"(a0), "r"(a1), "r"(a2), "r"(a3), "r"(b0), "r"(b1));
}

// ---- staging ----
__device__ __forceinline__ void stageA_hi(uint32_t dst0, const __half* __restrict__ ghi,
                                          int row0, int k0, int tid) {
    #pragma unroll
    for (int e = 0; e < 2; ++e) {                 // 64 rows x 16 segs
        int idx = tid + e * NTHR;
        int rem = idx & 1023, r = rem >> 4, seg = rem & 15;
        CP_ASYNC16(dst0 + (uint32_t)(r * 272 + seg * 16),
                   ghi + (size_t)(row0 + r) * 512 + k0 + seg * 8);
    }
}
__device__ __forceinline__ void stageB_hi(uint32_t dst0, const __half* __restrict__ ghi,
                                          int row0, int k0, int tid) {
    int r = tid >> 4, seg = tid & 15;             // 32 rows x 16 segs
    CP_ASYNC16(dst0 + (uint32_t)(r * 272 + seg * 16),
               ghi + (size_t)(row0 + r) * 512 + k0 + seg * 8);
}

// plain fp16 chunk: NKSH k16-steps, warp tile m16 x n16, 2 mma / k16
template<int NKSH>
__device__ __forceinline__ void chunk_plain(
    uint32_t aBase, uint32_t aStr,
    uint32_t bBase, uint32_t bStr,
    int mw, int nw, int lane, int ks0, float acc[2][4])
{
    const int m = lane >> 3, rr = lane & 7;
    const uint32_t aAddr = aBase + (uint32_t)(mw * 16 + (m & 1) * 8 + rr) * aStr
                         + (uint32_t)((m >> 1) * 16) + (uint32_t)(ks0 * 32);
    const uint32_t bAddr = bBase + (uint32_t)(nw * 16 + (m >> 1) * 8 + rr) * bStr
                         + (uint32_t)((m & 1) * 16) + (uint32_t)(ks0 * 32);
    #pragma unroll
    for (int ks = 0; ks < NKSH; ++ks) {
        uint32_t a0, a1, a2, a3;
        LDSM4(a0, a1, a2, a3, aAddr + ks * 32);
        uint32_t b0, b1, b2, b3;
        LDSM4(b0, b1, b2, b3, bAddr + ks * 32);
        mma16816(acc[0], a0, a1, a2, a3, b0, b1);
        mma16816(acc[1], a0, a1, a2, a3, b2, b3);
    }
}

__device__ __forceinline__ void grid_barrier(unsigned gen) {
    __syncthreads();
    if (threadIdx.x == 0) {
        __threadfence();
        if (atomicAdd(&g_bar_count, 1u) == (unsigned)(NCTA - 1)) {
            g_bar_count = 0u;
            __threadfence();
            g_bar_gen = gen + 1u;
        } else {
            while (g_bar_gen == gen) { }
            __threadfence();
        }
    }
    __syncthreads();
}
__device__ __forceinline__ void group_barrier(unsigned* cnt, volatile unsigned* gen,
                                              unsigned n, unsigned g) {
    __syncthreads();
    if (threadIdx.x == 0) {
        __threadfence();
        if (atomicAdd(cnt, 1u) == n - 1u) {
            *cnt = 0u;
            __threadfence();
            *gen = g + 1u;
        } else {
            while (*gen == g) { }
            __threadfence();
        }
    }
    __syncthreads();
}

__device__ __forceinline__ void kseg_reduce(uint32_t sb, int kseg, int mw, int nw,
                                            int lane, float acc[2][4]) {
    const uint32_t slot = sb + OFF_R + (uint32_t)(((mw * 2 + nw) * 32 + lane) * 32);
    if (kseg == 1) {
        asm volatile("st.shared.v4.f32 [%0], {%1,%2,%3,%4};" ::
            "r"(slot), "f"(acc[0][0]), "f"(acc[0][1]), "f"(acc[0][2]), "f"(acc[0][3]) : "memory");
        asm volatile("st.shared.v4.f32 [%0], {%1,%2,%3,%4};" ::
            "r"(slot + 16), "f"(acc[1][0]), "f"(acc[1][1]), "f"(acc[1][2]), "f"(acc[1][3]) : "memory");
    }
    __syncthreads();
    if (kseg == 0) {
        float4 v0, v1;
        asm volatile("ld.shared.v4.f32 {%0,%1,%2,%3}, [%4];"
            : "=f"(v0.x), "=f"(v0.y), "=f"(v0.z), "=f"(v0.w) : "r"(slot));
        asm volatile("ld.shared.v4.f32 {%0,%1,%2,%3}, [%4];"
            : "=f"(v1.x), "=f"(v1.y), "=f"(v1.z), "=f"(v1.w) : "r"(slot + 16));
        acc[0][0] += v0.x; acc[0][1] += v0.y; acc[0][2] += v0.z; acc[0][3] += v0.w;
        acc[1][0] += v1.x; acc[1][1] += v1.y; acc[1][2] += v1.z; acc[1][3] += v1.w;
    }
}

__global__ void __launch_bounds__(NTHR, 1) coesn_mma(
    const float* __restrict__ x,    const float* __restrict__ x2h,
    const float* __restrict__ h2h,  const float* __restrict__ h2hT,
    const float* __restrict__ bias, const float* __restrict__ gamma,
    const float* __restrict__ eps,  float* __restrict__ out, int write_final)
{
    extern __shared__ __align__(16) char smem[];
    const uint32_t sb = smem_u32(smem);
    const int tid = threadIdx.x;
    const int w = tid >> 5, lane = tid & 31;
    const int mw = w & 3, nw = (w >> 2) & 1, kseg = w >> 3;
    const int bidx = blockIdx.x;
    const int bt = bidx >> 4, ht = bidx & 15;
    const int b0 = bt * 64, h0 = ht * 32;

    unsigned gen = g_bar_gen;
    unsigned genc = g_cgen[ht * 32];
    unsigned genr = g_rgen[bt * 32];

    // ---- cooperative init ----
    const int gtid = bidx * NTHR + tid;
    #pragma unroll 1
    for (int e = 0; e < 4; ++e) {
        int idx = gtid + e * (NCTA * NTHR);
        int r = idx >> 9, c = idx & 511;
        g_W1_hi[idx] = __float2half_rn(h2h[(size_t)c * Hq + r]);   // W1[h=r][k=c]
        g_W2_hi[idx] = __float2half_rn(-h2hT[idx]);                // W2[b][j]
        g_hy_hi[0][idx] = __float2half_rn(0.f);
    }
    // BX = x2h^T slice hi: [32 h][32 i]
    #pragma unroll
    for (int e = 0; e < 2; ++e) {
        int idx = tid + e * NTHR;                  // 0..1023
        int r = idx >> 5, ii = idx & 31;
        *(__half*)(smem + OFF_BX + r * 80 + ii * 2) =
            __float2half_rn(x2h[(size_t)ii * Hq + h0 + r]);
    }
    if (tid < 32) {
        ((float*)(smem + OFF_SC))[tid]      = bias[h0 + tid];
        ((float*)(smem + OFF_SC))[32 + tid] = gamma[h0 + tid];
        ((float*)(smem + OFF_SC))[64 + tid] = eps[h0 + tid];
    }
    const float* scp = (const float*)(smem + OFF_SC);
    grid_barrier(gen); gen++;

    // ---- stage persistent weight slices (hi) ----
    #pragma unroll
    for (int e = 0; e < 4; ++e) {                  // W1P: 32 rows x 64 segs
        int idx = tid + e * NTHR;                  // 0..2047
        int r = idx >> 6, seg = idx & 63;
        CP_ASYNC16(sb + OFF_W1P + (uint32_t)(r * 1040 + seg * 16),
                   g_W1_hi + (size_t)(h0 + r) * 512 + seg * 8);
    }
    #pragma unroll
    for (int e = 0; e < 8; ++e) {                  // W2P: 64 rows x 64 segs
        int idx = tid + e * NTHR;                  // 0..4095
        int r = idx >> 6, seg = idx & 63;
        CP_ASYNC16(sb + OFF_W2P + (uint32_t)(r * 1040 + seg * 16),
                   g_W2_hi + (size_t)(b0 + r) * 512 + seg * 8);
    }
    CP_COMMIT(); CP_WAIT0();
    __syncthreads();

    float hyr[2][4], hzr[2][4];
    #pragma unroll
    for (int p = 0; p < 2; ++p)
        #pragma unroll
        for (int j = 0; j < 4; ++j) { hyr[p][j] = 0.f; hzr[p][j] = 0.f; }

    #pragma unroll 1
    for (int t = 0; t < Lq; ++t) {
        const int pt = t & 1;
        const __half* hyH = g_hy_hi[pt];
        const __half* TtH = g_Tt_hi[pt];

        // ===== Phase 1: D1 = hy @ h2h (A=hy hi streamed, B=W1P persistent) =====
        float acc[2][4];
        #pragma unroll
        for (int p = 0; p < 2; ++p)
            #pragma unroll
            for (int j = 0; j < 4; ++j) acc[p][j] = 0.f;

        stageA_hi(sb + OFF_A, hyH, b0, 0, tid);
        CP_COMMIT();
        stageA_hi(sb + OFF_A + A_BUF, hyH, b0, 128, tid);
        CP_COMMIT();
        #pragma unroll 1
        for (int kc = 0; kc < 4; ++kc) {
            if (kc < 3) { CP_WAIT1(); } else { CP_WAIT0(); }
            __syncthreads();
            if (kc + 2 < 4) {
                stageA_hi(sb + OFF_A + (uint32_t)((kc + 2) % 3) * A_BUF,
                          hyH, b0, (kc + 2) * 128, tid);
                CP_COMMIT();
            }
            chunk_plain<4>(sb + OFF_A + (uint32_t)(kc % 3) * A_BUF, 272u,
                           sb + OFF_W1P + (uint32_t)(kc * 256), W_STR,
                           mw, nw, lane, kseg * 4, acc);
        }
        kseg_reduce(sb, kseg, mw, nw, lane, acc);

        // tanh -> T smem (hi only; kseg0 warps)
        if (kseg == 0) {
            #pragma unroll
            for (int p = 0; p < 2; ++p) {
                #pragma unroll
                for (int j = 0; j < 4; ++j) {
                    int hc = nw * 16 + p * 8 + 2 * (lane & 3) + (j & 1);
                    int bl = mw * 16 + (lane >> 2) + ((j >> 1) * 8);
                    float v = acc[p][j] + scp[hc];
                    float e2 = __expf(2.f * v);
                    float tv = 1.f - 2.f / (e2 + 1.f);
                    *(__half*)(smem + OFF_T + hc * 144 + bl * 2) = __float2half_rn(tv);
                }
            }
        }
        __syncthreads();
        // x_t (hi) -> X smem (input-only; overlaps the column barrier wait)
        {
            int r = tid >> 3, q = tid & 7;
            float4 v = *(const float4*)(x + (size_t)(b0 + r) * (Lq * Iq)
                                          + (size_t)t * Iq + q * 4);
            char* dh = smem + OFF_X + r * 80 + q * 8;
            *(__half2*)(dh)     = __halves2half2(__float2half_rn(v.x), __float2half_rn(v.y));
            *(__half2*)(dh + 4) = __halves2half2(__float2half_rn(v.z), __float2half_rn(v.w));
        }
        // T -> global (parity buffer)
        if (tid < 256) {
            int r = tid >> 3, q = tid & 7;
            uint4 val = *(const uint4*)(smem + OFF_T + r * 144 + q * 16);
            *(uint4*)(g_Tt_hi[pt] + (size_t)(h0 + r) * 512 + b0 + q * 8) = val;
        }
        group_barrier(&g_ccnt[ht * 32], &g_cgen[ht * 32], 8u, genc); genc++;

        // ===== Phase 2: D2 = x_t @ x2h - h2hT @ T (A=W2P persistent, B=Tt streamed) =====
        stageB_hi(sb + OFF_B, TtH, h0, 0, tid);
        CP_COMMIT();
        stageB_hi(sb + OFF_B + B_BUF, TtH, h0, 128, tid);
        CP_COMMIT();
        #pragma unroll
        for (int p = 0; p < 2; ++p)
            #pragma unroll
            for (int j = 0; j < 4; ++j) acc[p][j] = 0.f;
        #pragma unroll 1
        for (int kc = 0; kc < 4; ++kc) {
            if (kc < 3) { CP_WAIT1(); } else { CP_WAIT0(); }
            __syncthreads();
            if (kc + 2 < 4) {
                stageB_hi(sb + OFF_B + (uint32_t)((kc + 2) % 3) * B_BUF,
                          TtH, h0, (kc + 2) * 128, tid);
                CP_COMMIT();
            }
            if (kc == 0) {
                chunk_plain<1>(sb + OFF_X, 80u, sb + OFF_BX, 80u,
                               mw, nw, lane, kseg, acc);
            }
            chunk_plain<4>(sb + OFF_W2P + (uint32_t)(kc * 256), W_STR,
                           sb + OFF_B + (uint32_t)(kc % 3) * B_BUF, 272u,
                           mw, nw, lane, kseg * 4, acc);
        }
        kseg_reduce(sb, kseg, mw, nw, lane, acc);

        // integrate (kseg0); hy -> O smem tile
        if (kseg == 0) {
            #pragma unroll
            for (int p = 0; p < 2; ++p) {
                #pragma unroll
                for (int j = 0; j < 4; ++j) {
                    int hc = nw * 16 + p * 8 + 2 * (lane & 3) + (j & 1);
                    int bl = mw * 16 + (lane >> 2) + ((j >> 1) * 8);
                    float hy = hyr[p][j], hz = hzr[p][j];
                    hz += DTF * (acc[p][j] - scp[32 + hc] * hy - scp[64 + hc] * hz);
                    hy += DTF * hz;
                    hzr[p][j] = hz; hyr[p][j] = hy;
                    *(float*)(smem + OFF_O + bl * 144 + hc * 4) = hy;
                }
            }
        }
        __syncthreads();
        {
            int r = tid >> 3, q = tid & 7;
            float4 v = *(const float4*)(smem + OFF_O + r * 144 + q * 16);
            *(float4*)(out + (size_t)(b0 + r) * (Lq * Hq) + (size_t)t * Hq
                           + h0 + q * 4) = v;
            size_t o = (size_t)(b0 + r) * 512 + h0 + q * 4;
            __half* hyD = g_hy_hi[(t + 1) & 1];
            *(__half2*)(hyD + o)     = __halves2half2(__float2half_rn(v.x),
                                                      __float2half_rn(v.y));
            *(__half2*)(hyD + o + 2) = __halves2half2(__float2half_rn(v.z),
                                                      __float2half_rn(v.w));
        }
        group_barrier(&g_rcnt[bt * 32], &g_rgen[bt * 32], 16u, genr); genr++;
    }

    // final hy (second output)
    if (write_final && kseg == 0) {
        #pragma unroll
        for (int p = 0; p < 2; ++p) {
            #pragma unroll
            for (int j = 0; j < 4; ++j) {
                int hc = nw * 16 + p * 8 + 2 * (lane & 3) + (j & 1);
                int bl = mw * 16 + (lane >> 2) + ((j >> 1) * 8);
                out[(size_t)Bq * Lq * Hq + (size_t)(b0 + bl) * Hq + h0 + hc] = hyr[p][j];
            }
        }
    }
}

extern "C" void kernel_launch(void* const* d_in, const int* in_sizes, int n_in,
                              void* d_out, int out_size) {
    const float* x    = (const float*)d_in[0];
    const float* x2h  = (const float*)d_in[1];
    const float* h2h  = (const float*)d_in[2];
    const float* h2hT = (const float*)d_in[3];
    const float* bias = (const float*)d_in[4];
    const float* gam  = (const float*)d_in[5];
    const float* eps  = (const float*)d_in[6];
    (void)in_sizes; (void)n_in;

    cudaFuncSetAttribute(coesn_mma, cudaFuncAttributeMaxDynamicSharedMemorySize, SMEM_TOT);
    const int write_final = (out_size >= Bq * Lq * Hq + Bq * Hq) ? 1 : 0;
    coesn_mma<<<NCTA, NTHR, SMEM_TOT>>>(x, x2h, h2h, h2hT, bias, gam, eps,
                                        (float*)d_out, write_final);
}

// round 17
// speedup vs baseline: 2.9953x; 1.0912x over previous
#include <cuda_runtime.h>
#include <cuda_fp16.h>
#include <cstdint>

#define Bq 512
#define Hq 512
#define Lq 512
#define Iq 32
#define DTF 0.042f
#define NCTA 128
#define NTHR 512

// ---- SMEM layout (bytes) ----
#define OFF_HYP  0        // full hy tile: 64 rows x 1040
#define OFF_TTP  66560    // full Tt tile: 32 rows x 1040
#define OFF_W1P  99840    // persistent W1 hi: 32 rows x 1040
#define OFF_W2P  133120   // persistent W2 hi: 64 rows x 1040
#define OFF_X    199680   // x hi: 64 x 80
#define OFF_BX   204800   // x2hT hi: 32 x 80
#define OFF_T    207360   // T hi: 32 x 144
#define OFF_O    211968   // 64 x 144 = 9216
#define OFF_R    221184   // kseg reduce: 8192
#define OFF_SC   229376   // 3 x 32 floats
#define SMEM_TOT 229760

#define W_STR   1040u

// ---- persistent device state (hy / Tt double-buffered by step parity) ----
__device__ __align__(256) __half g_hy_hi[2][Bq*Hq];
__device__ __align__(256) __half g_Tt_hi[2][Hq*Bq];        // T^T [h][b]
__device__ __align__(256) __half g_W1_hi[Hq*Hq];           // h2h^T: [h][k]
__device__ __align__(256) __half g_W2_hi[Hq*Hq];           // -h2hT: [b][j]
__device__ unsigned g_bar_count = 0u;
__device__ volatile unsigned g_bar_gen = 0u;
__device__ unsigned g_ccnt[16 * 32];
__device__ volatile unsigned g_cgen[16 * 32];
__device__ unsigned g_rcnt[8 * 32];
__device__ volatile unsigned g_rgen[8 * 32];

__device__ __forceinline__ uint32_t smem_u32(const void* p) {
    uint32_t a;
    asm("{ .reg .u64 t; cvta.to.shared.u64 t, %1; cvt.u32.u64 %0, t; }" : "=r"(a) : "l"(p));
    return a;
}
#define CP_ASYNC16(dst, src) \
    asm volatile("cp.async.cg.shared.global [%0], [%1], 16;" :: "r"(dst), "l"(src) : "memory")
#define CP_COMMIT() asm volatile("cp.async.commit_group;" ::: "memory")
#define CP_WAIT0()  asm volatile("cp.async.wait_group 0;" ::: "memory")
#define CP_WAIT1()  asm volatile("cp.async.wait_group 1;" ::: "memory")
#define LDSM4(r0,r1,r2,r3, addr) \
    asm volatile("ldmatrix.sync.aligned.m8n8.x4.shared.b16 {%0,%1,%2,%3}, [%4];" \
        : "=r"(r0), "=r"(r1), "=r"(r2), "=r"(r3) : "r"(addr))

__device__ __forceinline__ void mma16816(float* c, uint32_t a0, uint32_t a1, uint32_t a2,
                                         uint32_t a3, uint32_t b0, uint32_t b1) {
    asm volatile(
        "mma.sync.aligned.m16n8k16.row.col.f32.f16.f16.f32 "
        "{%0,%1,%2,%3}, {%4,%5,%6,%7}, {%8,%9}, {%0,%1,%2,%3};"
        : "+f"(c[0]), "+f"(c[1]), "+f"(c[2]), "+f"(c[3])
        : "r"(a0), "r"(a1), "r"(a2), "r"(a3), "r"(b0), "r"(b1));
}

// ---- staging: half of a persistent-layout tile (stride 1040) ----
__device__ __forceinline__ void stage_hy_half(uint32_t sb, const __half* __restrict__ g,
                                              int b0, int half, int tid) {
    #pragma unroll
    for (int e = 0; e < 4; ++e) {                 // 64 rows x 32 segs
        int idx = tid + e * NTHR;
        int r = idx >> 5, seg = idx & 31;
        CP_ASYNC16(sb + OFF_HYP + (uint32_t)(r * 1040 + (half * 32 + seg) * 16),
                   g + (size_t)(b0 + r) * 512 + half * 256 + seg * 8);
    }
}
__device__ __forceinline__ void stage_tt_half(uint32_t sb, const __half* __restrict__ g,
                                              int h0, int half, int tid) {
    #pragma unroll
    for (int e = 0; e < 2; ++e) {                 // 32 rows x 32 segs
        int idx = tid + e * NTHR;
        int r = idx >> 5, seg = idx & 31;
        CP_ASYNC16(sb + OFF_TTP + (uint32_t)(r * 1040 + (half * 32 + seg) * 16),
                   g + (size_t)(h0 + r) * 512 + half * 256 + seg * 8);
    }
}

// plain fp16 chunk: NKSH k16-steps, warp tile m16 x n16, 2 mma / k16
template<int NKSH>
__device__ __forceinline__ void chunk_plain(
    uint32_t aBase, uint32_t aStr,
    uint32_t bBase, uint32_t bStr,
    int mw, int nw, int lane, int ks0, float acc[2][4])
{
    const int m = lane >> 3, rr = lane & 7;
    const uint32_t aAddr = aBase + (uint32_t)(mw * 16 + (m & 1) * 8 + rr) * aStr
                         + (uint32_t)((m >> 1) * 16) + (uint32_t)(ks0 * 32);
    const uint32_t bAddr = bBase + (uint32_t)(nw * 16 + (m >> 1) * 8 + rr) * bStr
                         + (uint32_t)((m & 1) * 16) + (uint32_t)(ks0 * 32);
    #pragma unroll
    for (int ks = 0; ks < NKSH; ++ks) {
        uint32_t a0, a1, a2, a3;
        LDSM4(a0, a1, a2, a3, aAddr + ks * 32);
        uint32_t b0, b1, b2, b3;
        LDSM4(b0, b1, b2, b3, bAddr + ks * 32);
        mma16816(acc[0], a0, a1, a2, a3, b0, b1);
        mma16816(acc[1], a0, a1, a2, a3, b2, b3);
    }
}

__device__ __forceinline__ void grid_barrier(unsigned gen) {
    __syncthreads();
    if (threadIdx.x == 0) {
        __threadfence();
        if (atomicAdd(&g_bar_count, 1u) == (unsigned)(NCTA - 1)) {
            g_bar_count = 0u;
            __threadfence();
            g_bar_gen = gen + 1u;
        } else {
            while (g_bar_gen == gen) { }
            __threadfence();
        }
    }
    __syncthreads();
}
__device__ __forceinline__ void group_barrier(unsigned* cnt, volatile unsigned* gen,
                                              unsigned n, unsigned g) {
    __syncthreads();
    if (threadIdx.x == 0) {
        __threadfence();
        if (atomicAdd(cnt, 1u) == n - 1u) {
            *cnt = 0u;
            __threadfence();
            *gen = g + 1u;
        } else {
            while (*gen == g) { }
            __threadfence();
        }
    }
    __syncthreads();
}

__device__ __forceinline__ void kseg_reduce(uint32_t sb, int kseg, int mw, int nw,
                                            int lane, float acc[2][4]) {
    const uint32_t slot = sb + OFF_R + (uint32_t)(((mw * 2 + nw) * 32 + lane) * 32);
    if (kseg == 1) {
        asm volatile("st.shared.v4.f32 [%0], {%1,%2,%3,%4};" ::
            "r"(slot), "f"(acc[0][0]), "f"(acc[0][1]), "f"(acc[0][2]), "f"(acc[0][3]) : "memory");
        asm volatile("st.shared.v4.f32 [%0], {%1,%2,%3,%4};" ::
            "r"(slot + 16), "f"(acc[1][0]), "f"(acc[1][1]), "f"(acc[1][2]), "f"(acc[1][3]) : "memory");
    }
    __syncthreads();
    if (kseg == 0) {
        float4 v0, v1;
        asm volatile("ld.shared.v4.f32 {%0,%1,%2,%3}, [%4];"
            : "=f"(v0.x), "=f"(v0.y), "=f"(v0.z), "=f"(v0.w) : "r"(slot));
        asm volatile("ld.shared.v4.f32 {%0,%1,%2,%3}, [%4];"
            : "=f"(v1.x), "=f"(v1.y), "=f"(v1.z), "=f"(v1.w) : "r"(slot + 16));
        acc[0][0] += v0.x; acc[0][1] += v0.y; acc[0][2] += v0.z; acc[0][3] += v0.w;
        acc[1][0] += v1.x; acc[1][1] += v1.y; acc[1][2] += v1.z; acc[1][3] += v1.w;
    }
}

__global__ void __launch_bounds__(NTHR, 1) coesn_mma(
    const float* __restrict__ x,    const float* __restrict__ x2h,
    const float* __restrict__ h2h,  const float* __restrict__ h2hT,
    const float* __restrict__ bias, const float* __restrict__ gamma,
    const float* __restrict__ eps,  float* __restrict__ out, int write_final)
{
    extern __shared__ __align__(16) char smem[];
    const uint32_t sb = smem_u32(smem);
    const int tid = threadIdx.x;
    const int w = tid >> 5, lane = tid & 31;
    const int mw = w & 3, nw = (w >> 2) & 1, kseg = w >> 3;
    const int bidx = blockIdx.x;
    const int bt = bidx >> 4, ht = bidx & 15;
    const int b0 = bt * 64, h0 = ht * 32;

    unsigned gen = g_bar_gen;
    unsigned genc = g_cgen[ht * 32];
    unsigned genr = g_rgen[bt * 32];

    // ---- cooperative init ----
    const int gtid = bidx * NTHR + tid;
    #pragma unroll 1
    for (int e = 0; e < 4; ++e) {
        int idx = gtid + e * (NCTA * NTHR);
        int r = idx >> 9, c = idx & 511;
        g_W1_hi[idx] = __float2half_rn(h2h[(size_t)c * Hq + r]);   // W1[h=r][k=c]
        g_W2_hi[idx] = __float2half_rn(-h2hT[idx]);                // W2[b][j]
        g_hy_hi[0][idx] = __float2half_rn(0.f);
    }
    // BX = x2h^T slice hi: [32 h][32 i]
    #pragma unroll
    for (int e = 0; e < 2; ++e) {
        int idx = tid + e * NTHR;
        int r = idx >> 5, ii = idx & 31;
        *(__half*)(smem + OFF_BX + r * 80 + ii * 2) =
            __float2half_rn(x2h[(size_t)ii * Hq + h0 + r]);
    }
    if (tid < 32) {
        ((float*)(smem + OFF_SC))[tid]      = bias[h0 + tid];
        ((float*)(smem + OFF_SC))[32 + tid] = gamma[h0 + tid];
        ((float*)(smem + OFF_SC))[64 + tid] = eps[h0 + tid];
    }
    const float* scp = (const float*)(smem + OFF_SC);
    grid_barrier(gen); gen++;

    // ---- stage persistent weight slices ----
    #pragma unroll
    for (int e = 0; e < 4; ++e) {                  // W1P: 32 rows x 64 segs
        int idx = tid + e * NTHR;
        int r = idx >> 6, seg = idx & 63;
        CP_ASYNC16(sb + OFF_W1P + (uint32_t)(r * 1040 + seg * 16),
                   g_W1_hi + (size_t)(h0 + r) * 512 + seg * 8);
    }
    #pragma unroll
    for (int e = 0; e < 8; ++e) {                  // W2P: 64 rows x 64 segs
        int idx = tid + e * NTHR;
        int r = idx >> 6, seg = idx & 63;
        CP_ASYNC16(sb + OFF_W2P + (uint32_t)(r * 1040 + seg * 16),
                   g_W2_hi + (size_t)(b0 + r) * 512 + seg * 8);
    }
    CP_COMMIT(); CP_WAIT0();
    // x(0) -> X smem
    {
        int r = tid >> 3, q = tid & 7;
        float4 v = *(const float4*)(x + (size_t)(b0 + r) * (Lq * Iq) + q * 4);
        char* dh = smem + OFF_X + r * 80 + q * 8;
        *(__half2*)(dh)     = __halves2half2(__float2half_rn(v.x), __float2half_rn(v.y));
        *(__half2*)(dh + 4) = __halves2half2(__float2half_rn(v.z), __float2half_rn(v.w));
    }
    __syncthreads();

    float hyr[2][4], hzr[2][4];
    #pragma unroll
    for (int p = 0; p < 2; ++p)
        #pragma unroll
        for (int j = 0; j < 4; ++j) { hyr[p][j] = 0.f; hzr[p][j] = 0.f; }

    #pragma unroll 1
    for (int t = 0; t < Lq; ++t) {
        const int pt = t & 1;
        const __half* hyH = g_hy_hi[pt];
        const __half* TtH = g_Tt_hi[pt];

        // ===== Phase 1: stage hy halves; x-term in the staging shadow =====
        stage_hy_half(sb, hyH, b0, 0, tid); CP_COMMIT();
        stage_hy_half(sb, hyH, b0, 1, tid); CP_COMMIT();

        float acc2[2][4];                           // phase-2 accumulator (x-term)
        #pragma unroll
        for (int p = 0; p < 2; ++p)
            #pragma unroll
            for (int j = 0; j < 4; ++j) acc2[p][j] = 0.f;
        chunk_plain<1>(sb + OFF_X, 80u, sb + OFF_BX, 80u, mw, nw, lane, kseg, acc2);

        float acc[2][4];
        #pragma unroll
        for (int p = 0; p < 2; ++p)
            #pragma unroll
            for (int j = 0; j < 4; ++j) acc[p][j] = 0.f;

        CP_WAIT1(); __syncthreads();
        chunk_plain<4>(sb + OFF_HYP,        W_STR, sb + OFF_W1P,        W_STR,
                       mw, nw, lane, kseg * 4, acc);
        chunk_plain<4>(sb + OFF_HYP + 256u, W_STR, sb + OFF_W1P + 256u, W_STR,
                       mw, nw, lane, kseg * 4, acc);
        CP_WAIT0(); __syncthreads();
        chunk_plain<4>(sb + OFF_HYP + 512u, W_STR, sb + OFF_W1P + 512u, W_STR,
                       mw, nw, lane, kseg * 4, acc);
        chunk_plain<4>(sb + OFF_HYP + 768u, W_STR, sb + OFF_W1P + 768u, W_STR,
                       mw, nw, lane, kseg * 4, acc);
        kseg_reduce(sb, kseg, mw, nw, lane, acc);

        // tanh -> T smem (kseg0)
        if (kseg == 0) {
            #pragma unroll
            for (int p = 0; p < 2; ++p) {
                #pragma unroll
                for (int j = 0; j < 4; ++j) {
                    int hc = nw * 16 + p * 8 + 2 * (lane & 3) + (j & 1);
                    int bl = mw * 16 + (lane >> 2) + ((j >> 1) * 8);
                    float v = acc[p][j] + scp[hc];
                    float e2 = __expf(2.f * v);
                    float tv = 1.f - 2.f / (e2 + 1.f);
                    *(__half*)(smem + OFF_T + hc * 144 + bl * 2) = __float2half_rn(tv);
                }
            }
        }
        __syncthreads();
        if (tid < 256) {                            // T -> global parity buffer
            int r = tid >> 3, q = tid & 7;
            uint4 val = *(const uint4*)(smem + OFF_T + r * 144 + q * 16);
            *(uint4*)(g_Tt_hi[pt] + (size_t)(h0 + r) * 512 + b0 + q * 8) = val;
        }
        group_barrier(&g_ccnt[ht * 32], &g_cgen[ht * 32], 8u, genc); genc++;

        // ===== Phase 2: stage Tt halves; x(t+1) in the staging shadow =====
        stage_tt_half(sb, TtH, h0, 0, tid); CP_COMMIT();
        stage_tt_half(sb, TtH, h0, 1, tid); CP_COMMIT();
        {
            int tn = (t + 1 < Lq) ? (t + 1) : t;    // stage next x (X dead this phase)
            int r = tid >> 3, q = tid & 7;
            float4 v = *(const float4*)(x + (size_t)(b0 + r) * (Lq * Iq)
                                          + (size_t)tn * Iq + q * 4);
            char* dh = smem + OFF_X + r * 80 + q * 8;
            *(__half2*)(dh)     = __halves2half2(__float2half_rn(v.x), __float2half_rn(v.y));
            *(__half2*)(dh + 4) = __halves2half2(__float2half_rn(v.z), __float2half_rn(v.w));
        }
        CP_WAIT1(); __syncthreads();
        chunk_plain<4>(sb + OFF_W2P,        W_STR, sb + OFF_TTP,        W_STR,
                       mw, nw, lane, kseg * 4, acc2);
        chunk_plain<4>(sb + OFF_W2P + 256u, W_STR, sb + OFF_TTP + 256u, W_STR,
                       mw, nw, lane, kseg * 4, acc2);
        CP_WAIT0(); __syncthreads();
        chunk_plain<4>(sb + OFF_W2P + 512u, W_STR, sb + OFF_TTP + 512u, W_STR,
                       mw, nw, lane, kseg * 4, acc2);
        chunk_plain<4>(sb + OFF_W2P + 768u, W_STR, sb + OFF_TTP + 768u, W_STR,
                       mw, nw, lane, kseg * 4, acc2);
        kseg_reduce(sb, kseg, mw, nw, lane, acc2);

        // integrate (kseg0); hy -> O smem
        if (kseg == 0) {
            #pragma unroll
            for (int p = 0; p < 2; ++p) {
                #pragma unroll
                for (int j = 0; j < 4; ++j) {
                    int hc = nw * 16 + p * 8 + 2 * (lane & 3) + (j & 1);
                    int bl = mw * 16 + (lane >> 2) + ((j >> 1) * 8);
                    float hy = hyr[p][j], hz = hzr[p][j];
                    hz += DTF * (acc2[p][j] - scp[32 + hc] * hy - scp[64 + hc] * hz);
                    hy += DTF * hz;
                    hzr[p][j] = hz; hyr[p][j] = hy;
                    *(float*)(smem + OFF_O + bl * 144 + hc * 4) = hy;
                }
            }
        }
        __syncthreads();
        {
            int r = tid >> 3, q = tid & 7;
            float4 v = *(const float4*)(smem + OFF_O + r * 144 + q * 16);
            *(float4*)(out + (size_t)(b0 + r) * (Lq * Hq) + (size_t)t * Hq
                           + h0 + q * 4) = v;
            size_t o = (size_t)(b0 + r) * 512 + h0 + q * 4;
            __half* hyD = g_hy_hi[(t + 1) & 1];
            *(__half2*)(hyD + o)     = __halves2half2(__float2half_rn(v.x),
                                                      __float2half_rn(v.y));
            *(__half2*)(hyD + o + 2) = __halves2half2(__float2half_rn(v.z),
                                                      __float2half_rn(v.w));
        }
        group_barrier(&g_rcnt[bt * 32], &g_rgen[bt * 32], 16u, genr); genr++;
    }

    // final hy (second output)
    if (write_final && kseg == 0) {
        #pragma unroll
        for (int p = 0; p < 2; ++p) {
            #pragma unroll
            for (int j = 0; j < 4; ++j) {
                int hc = nw * 16 + p * 8 + 2 * (lane & 3) + (j & 1);
                int bl = mw * 16 + (lane >> 2) + ((j >> 1) * 8);
                out[(size_t)Bq * Lq * Hq + (size_t)(b0 + bl) * Hq + h0 + hc] = hyr[p][j];
            }
        }
    }
}

extern "C" void kernel_launch(void* const* d_in, const int* in_sizes, int n_in,
                              void* d_out, int out_size) {
    const float* x    = (const float*)d_in[0];
    const float* x2h  = (const float*)d_in[1];
    const float* h2h  = (const float*)d_in[2];
    const float* h2hT = (const float*)d_in[3];
    const float* bias = (const float*)d_in[4];
    const float* gam  = (const float*)d_in[5];
    const float* eps  = (const float*)d_in[6];
    (void)in_sizes; (void)n_in;

    cudaFuncSetAttribute(coesn_mma, cudaFuncAttributeMaxDynamicSharedMemorySize, SMEM_TOT);
    const int write_final = (out_size >= Bq * Lq * Hq + Bq * Hq) ? 1 : 0;
    coesn_mma<<<NCTA, NTHR, SMEM_TOT>>>(x, x2h, h2h, h2hT, bias, gam, eps,
                                        (float*)d_out, write_final);
}